// round 10
// baseline (speedup 1.0000x reference)
#include <cuda_runtime.h>
#include <cuda_bf16.h>
#include <math_constants.h>
#include <math.h>
#include <cstdint>

#define DIMN 2048
#define BB 2
#define SS 2048
#define HH 16
#define HDD 128
#define MTOT (BB*SS)   // 4096

// ---------------------------------------------------------------------------
// Scratch (alloc-free rule: __device__ globals)
// ---------------------------------------------------------------------------
__device__ __nv_bfloat16 g_xh[(size_t)MTOT * DIMN];
__device__ __nv_bfloat16 g_xl[(size_t)MTOT * DIMN];
__device__ __nv_bfloat16 g_ath[(size_t)MTOT * DIMN];
__device__ __nv_bfloat16 g_atl[(size_t)MTOT * DIMN];
__device__ __nv_bfloat16 g_wth[4][(size_t)DIMN * DIMN];   // W^T hi, [N][K]
__device__ __nv_bfloat16 g_wtl[4][(size_t)DIMN * DIMN];   // W^T lo
__device__ __nv_bfloat16 g_qh[(size_t)MTOT * DIMN];
__device__ __nv_bfloat16 g_ql[(size_t)MTOT * DIMN];
__device__ __nv_bfloat16 g_kh[(size_t)MTOT * DIMN];
__device__ __nv_bfloat16 g_kl[(size_t)MTOT * DIMN];
__device__ __nv_bfloat16 g_vh[(size_t)MTOT * DIMN];
__device__ __nv_bfloat16 g_vl[(size_t)MTOT * DIMN];

// ---------------------------------------------------------------------------
// PTX helpers (generic sm_80+ features only)
// ---------------------------------------------------------------------------
__device__ __forceinline__ void cp_async16_s(uint32_t s, const void* g) {
    asm volatile("cp.async.cg.shared.global [%0], [%1], 16;\n" :: "r"(s), "l"(g));
}
#define CP_COMMIT() asm volatile("cp.async.commit_group;\n")

__device__ __forceinline__ uint32_t smem_u32(const void* p) {
    uint32_t a;
    asm("{ .reg .u64 t; cvta.to.shared.u64 t, %1; cvt.u32.u64 %0, t; }"
        : "=r"(a) : "l"(p));
    return a;
}

__device__ __forceinline__ void ldsm_x4(uint32_t addr, uint32_t* r) {
    asm volatile("ldmatrix.sync.aligned.m8n8.x4.shared.b16 {%0,%1,%2,%3}, [%4];"
                 : "=r"(r[0]), "=r"(r[1]), "=r"(r[2]), "=r"(r[3]) : "r"(addr));
}
__device__ __forceinline__ void ldsm_x4_t(uint32_t addr, uint32_t* r) {
    asm volatile("ldmatrix.sync.aligned.m8n8.x4.trans.shared.b16 {%0,%1,%2,%3}, [%4];"
                 : "=r"(r[0]), "=r"(r[1]), "=r"(r[2]), "=r"(r[3]) : "r"(addr));
}

__device__ __forceinline__ void mma_bf16(float* d, const uint32_t* a,
                                         const uint32_t* b) {
    asm volatile(
        "mma.sync.aligned.m16n8k16.row.col.f32.bf16.bf16.f32 "
        "{%0,%1,%2,%3}, {%4,%5,%6,%7}, {%8,%9}, {%0,%1,%2,%3};"
        : "+f"(d[0]), "+f"(d[1]), "+f"(d[2]), "+f"(d[3])
        : "r"(a[0]), "r"(a[1]), "r"(a[2]), "r"(a[3]), "r"(b[0]), "r"(b[1]));
}

__device__ __forceinline__ void split_store(__nv_bfloat16* h, __nv_bfloat16* l,
                                            size_t off, float v0, float v1) {
    __nv_bfloat16 h0 = __float2bfloat16(v0), h1 = __float2bfloat16(v1);
    *(__nv_bfloat162*)(h + off) = __nv_bfloat162(h0, h1);
    *(__nv_bfloat162*)(l + off) = __nv_bfloat162(
        __float2bfloat16(v0 - __bfloat162float(h0)),
        __float2bfloat16(v1 - __bfloat162float(h1)));
}

// ---------------------------------------------------------------------------
// Prep: split fp32 rows into bf16 hi/lo
// ---------------------------------------------------------------------------
__global__ void split_rows(const float* __restrict__ in,
                           __nv_bfloat16* __restrict__ h,
                           __nv_bfloat16* __restrict__ l) {
    size_t i = ((size_t)blockIdx.x * 256 + threadIdx.x) * 4;
    float4 v = *(const float4*)(in + i);
    __nv_bfloat16 h0 = __float2bfloat16(v.x), h1 = __float2bfloat16(v.y);
    __nv_bfloat16 h2 = __float2bfloat16(v.z), h3 = __float2bfloat16(v.w);
    *(__nv_bfloat162*)(h + i)     = __nv_bfloat162(h0, h1);
    *(__nv_bfloat162*)(h + i + 2) = __nv_bfloat162(h2, h3);
    *(__nv_bfloat162*)(l + i) = __nv_bfloat162(
        __float2bfloat16(v.x - __bfloat162float(h0)),
        __float2bfloat16(v.y - __bfloat162float(h1)));
    *(__nv_bfloat162*)(l + i + 2) = __nv_bfloat162(
        __float2bfloat16(v.z - __bfloat162float(h2)),
        __float2bfloat16(v.w - __bfloat162float(h3)));
}

// ---------------------------------------------------------------------------
// Prep: transpose W -> W^T and split into bf16 hi/lo
// ---------------------------------------------------------------------------
__global__ void split_transpose(const float* __restrict__ W,
                                __nv_bfloat16* __restrict__ th,
                                __nv_bfloat16* __restrict__ tl) {
    __shared__ float ts[32][33];
    const int bx = blockIdx.x * 32, by = blockIdx.y * 32;
    const int tx = threadIdx.x, ty = threadIdx.y;   // 32 x 8
    #pragma unroll
    for (int j = 0; j < 4; j++)
        ts[ty + 8 * j][tx] = W[(size_t)(by + ty + 8 * j) * DIMN + bx + tx];
    __syncthreads();
    #pragma unroll
    for (int j = 0; j < 4; j++) {
        float v = ts[tx][ty + 8 * j];
        __nv_bfloat16 h = __float2bfloat16(v);
        __nv_bfloat16 l = __float2bfloat16(v - __bfloat162float(h));
        size_t o = (size_t)(bx + ty + 8 * j) * DIMN + by + tx;
        th[o] = h;
        tl[o] = l;
    }
}

// ---------------------------------------------------------------------------
// bf16 3-term split GEMM, 128x128x32, 512 threads, 3-stage cp.async.
// MODE 0: QKV epilogue — apply RoPE (mats 0,1) in fp32, emit bf16 hi/lo.
// MODE 1: plain fp32 epilogue to C.
// ---------------------------------------------------------------------------
#define BKT 32
#define ROWB 80
#define ASTRIDE (128 * ROWB)
#define STG_BYTES (4 * ASTRIDE)
#define NSTAGE 3
#define GSMEM (NSTAGE * STG_BYTES)

__device__ __forceinline__ void fill_stage(uint32_t stg,
        const __nv_bfloat16* ah, const __nv_bfloat16* al,
        const __nv_bfloat16* bh, const __nv_bfloat16* bl,
        int k0, int t) {
    int row = t >> 2, cc = t & 3;
    uint32_t so = (uint32_t)(row * ROWB + cc * 16);
    size_t g = (size_t)row * DIMN + k0 + cc * 8;
    cp_async16_s(stg + so,               ah + g);
    cp_async16_s(stg + ASTRIDE + so,     al + g);
    cp_async16_s(stg + 2 * ASTRIDE + so, bh + g);
    cp_async16_s(stg + 3 * ASTRIDE + so, bl + g);
}

template <int MODE>
__global__ __launch_bounds__(512)
void hgemm3(const __nv_bfloat16* __restrict__ Ah, const __nv_bfloat16* __restrict__ Al,
            const __nv_bfloat16* __restrict__ Bh, const __nv_bfloat16* __restrict__ Bl,
            float* __restrict__ C,
            __nv_bfloat16* __restrict__ qh, __nv_bfloat16* __restrict__ ql,
            __nv_bfloat16* __restrict__ kh, __nv_bfloat16* __restrict__ kl,
            __nv_bfloat16* __restrict__ vh, __nv_bfloat16* __restrict__ vl,
            int mat0) {
    extern __shared__ char dsm[];
    const uint32_t base = smem_u32(dsm);

    const int t    = threadIdx.x;
    const int lane = t & 31;
    const int warp = t >> 5;
    const int wm   = warp & 3;
    const int wn   = warp >> 2;
    const int bm   = blockIdx.y << 7;
    const int bn   = blockIdx.x << 7;

    const __nv_bfloat16* ah0 = Ah + (size_t)bm * DIMN;
    const __nv_bfloat16* al0 = Al + (size_t)bm * DIMN;
    const __nv_bfloat16* bh0 = Bh + (size_t)bn * DIMN;
    const __nv_bfloat16* bl0 = Bl + (size_t)bn * DIMN;

    const int nloc = bn & 2047;

    float acc[2][4][4];
    #pragma unroll
    for (int mi = 0; mi < 2; mi++)
        #pragma unroll
        for (int ni = 0; ni < 4; ni++)
            #pragma unroll
            for (int e = 0; e < 4; e++) acc[mi][ni][e] = 0.f;

    const uint32_t a_lrow  = (uint32_t)(lane & 15);
    const uint32_t a_khalf = (uint32_t)(lane >> 4) * 16;

    fill_stage(base, ah0, al0, bh0, bl0, 0, t);
    CP_COMMIT();
    fill_stage(base + STG_BYTES, ah0, al0, bh0, bl0, BKT, t);
    CP_COMMIT();

    const int NT = DIMN / BKT;
    uint32_t sidx = 0, fidx = 2;
    for (int kt = 0; kt < NT; kt++) {
        if (kt + 2 < NT) {
            fill_stage(base + fidx * STG_BYTES, ah0, al0, bh0, bl0,
                       (kt + 2) * BKT, t);
            CP_COMMIT();
            asm volatile("cp.async.wait_group 2;\n");
        } else {
            asm volatile("cp.async.wait_group 0;\n");
        }
        __syncthreads();

        const uint32_t stg  = base + sidx * STG_BYTES;
        const uint32_t As_h = stg;
        const uint32_t As_l = stg + ASTRIDE;
        const uint32_t Bs_h = stg + 2 * ASTRIDE;
        const uint32_t Bs_l = stg + 3 * ASTRIDE;

        #pragma unroll
        for (int ks = 0; ks < 2; ks++) {
            const uint32_t kb = (uint32_t)ks * 32;
            // B fragments: 2 x4 pair-loads per array (r0/r2 -> nj*2, r1/r3 -> nj*2+1)
            uint32_t Bfh[4][2], Bfl[4][2];
            #pragma unroll
            for (int nj = 0; nj < 2; nj++) {
                uint32_t ro = (uint32_t)(wn * 32 + nj * 16) + a_lrow;
                uint32_t off = ro * ROWB + kb + a_khalf;
                uint32_t rh[4], rl[4];
                ldsm_x4(Bs_h + off, rh);
                ldsm_x4(Bs_l + off, rl);
                Bfh[2*nj][0] = rh[0]; Bfh[2*nj][1] = rh[2];
                Bfh[2*nj+1][0] = rh[1]; Bfh[2*nj+1][1] = rh[3];
                Bfl[2*nj][0] = rl[0]; Bfl[2*nj][1] = rl[2];
                Bfl[2*nj+1][0] = rl[1]; Bfl[2*nj+1][1] = rl[3];
            }
            #pragma unroll
            for (int mi = 0; mi < 2; mi++) {
                uint32_t ro = (uint32_t)(wm * 32 + mi * 16) + a_lrow;
                uint32_t off = ro * ROWB + kb + a_khalf;
                uint32_t Afh[4], Afl[4];
                ldsm_x4(As_h + off, Afh);
                ldsm_x4(As_l + off, Afl);
                #pragma unroll
                for (int ni = 0; ni < 4; ni++) {
                    mma_bf16(acc[mi][ni], Afh, Bfh[ni]);
                    mma_bf16(acc[mi][ni], Afl, Bfh[ni]);
                    mma_bf16(acc[mi][ni], Afh, Bfl[ni]);
                }
            }
        }
        __syncthreads();

        sidx = (sidx + 1 == NSTAGE) ? 0 : sidx + 1;
        fidx = (fidx + 1 == NSTAGE) ? 0 : fidx + 1;
    }

    const int gr = lane >> 2, tg = lane & 3;
    if (MODE == 1) {
        #pragma unroll
        for (int mi = 0; mi < 2; mi++) {
            #pragma unroll
            for (int ni = 0; ni < 4; ni++) {
                const int m = bm + wm * 32 + mi * 16 + gr;
                const int n = nloc + wn * 32 + ni * 8 + tg * 2;
                *(float2*)(C + (size_t)m * DIMN + n) =
                    make_float2(acc[mi][ni][0], acc[mi][ni][1]);
                *(float2*)(C + (size_t)(m + 8) * DIMN + n) =
                    make_float2(acc[mi][ni][2], acc[mi][ni][3]);
            }
        }
    } else {
        const int gm = mat0 + (bn >> 11);
        __nv_bfloat16 *oh, *ol;
        if (gm == 0)      { oh = qh; ol = ql; }
        else if (gm == 1) { oh = kh; ol = kl; }
        else              { oh = vh; ol = vl; }
        const bool dorope = (gm < 2);
        #pragma unroll
        for (int mi = 0; mi < 2; mi++) {
            #pragma unroll
            for (int ni = 0; ni < 4; ni++) {
                const int n  = nloc + wn * 32 + ni * 8 + tg * 2;
                const int r0 = bm + wm * 32 + mi * 16 + gr;
                float v0 = acc[mi][ni][0], v1 = acc[mi][ni][1];
                float v2 = acc[mi][ni][2], v3 = acc[mi][ni][3];
                if (dorope) {
                    int dp = (n >> 1) & 63;
                    float inv = powf(10000.0f, -(float)dp * (1.0f / 64.0f));
                    float sn0, cs0, sn1, cs1;
                    sincosf((float)(r0 & (SS - 1)) * inv, &sn0, &cs0);
                    sincosf((float)((r0 + 8) & (SS - 1)) * inv, &sn1, &cs1);
                    float t0 = v0 * cs0 - v1 * sn0, t1 = v0 * sn0 + v1 * cs0;
                    v0 = t0; v1 = t1;
                    float t2 = v2 * cs1 - v3 * sn1, t3 = v2 * sn1 + v3 * cs1;
                    v2 = t2; v3 = t3;
                }
                split_store(oh, ol, (size_t)r0 * DIMN + n, v0, v1);
                split_store(oh, ol, (size_t)(r0 + 8) * DIMN + n, v2, v3);
            }
        }
    }
}

// ---------------------------------------------------------------------------
// flash2: tensor-core causal flash attention, BM=BN=64, 256 threads.
// Emits output directly as bf16 hi/lo (ath/atl) for the O-projection.
// ---------------------------------------------------------------------------
#define FRB 272                 // Q/K/V smem row bytes (128 bf16 + 8 pad)
#define PRB 144                 // P smem row bytes (64 bf16 + 8 pad)
#define SST 66                  // Ss fp32 stride
#define OFF_QH 0
#define OFF_QL 17408
#define OFF_KH 34816
#define OFF_KL 52224
#define OFF_VH 69632
#define OFF_VL 87040
#define OFF_SSX 104448
#define OFF_PH 121344
#define OFF_PL 130560
#define OFF_CORR 139776
#define OFF_LINV 140032
#define FLASH2_SMEM 140288

__global__ __launch_bounds__(256, 1)
void flash2(const __nv_bfloat16* __restrict__ Qh, const __nv_bfloat16* __restrict__ Ql,
            const __nv_bfloat16* __restrict__ Kh, const __nv_bfloat16* __restrict__ Kl,
            const __nv_bfloat16* __restrict__ Vh, const __nv_bfloat16* __restrict__ Vl,
            __nv_bfloat16* __restrict__ Ath, __nv_bfloat16* __restrict__ Atl) {
    extern __shared__ char fsm[];
    const uint32_t base = smem_u32(fsm);
    float* Ssf    = (float*)(fsm + OFF_SSX);
    float* scorrf = (float*)(fsm + OFF_CORR);
    float* linvf  = (float*)(fsm + OFF_LINV);
    __nv_bfloat16* Psh = (__nv_bfloat16*)(fsm + OFF_PH);
    __nv_bfloat16* Psl = (__nv_bfloat16*)(fsm + OFF_PL);

    const int t = threadIdx.x, lane = t & 31, warp = t >> 5;
    const int qt = blockIdx.x, h = blockIdx.y, b = blockIdx.z;
    const int q0 = qt * 64;
    const float scale = 0.08838834764831845f;   // 1/sqrt(128)

    const size_t hoff = ((size_t)b * SS) * DIMN + (size_t)h * HDD;
    const __nv_bfloat16* qh = Qh + hoff;
    const __nv_bfloat16* ql = Ql + hoff;
    const __nv_bfloat16* kh = Kh + hoff;
    const __nv_bfloat16* kl = Kl + hoff;
    const __nv_bfloat16* vh = Vh + hoff;
    const __nv_bfloat16* vl = Vl + hoff;

    #pragma unroll
    for (int i = 0; i < 4; i++) {
        int c = t + (i << 8);
        int row = c >> 4, cc = c & 15;
        uint32_t so = (uint32_t)(row * FRB + cc * 16);
        size_t g = (size_t)(q0 + row) * DIMN + cc * 8;
        cp_async16_s(base + OFF_QH + so, qh + g);
        cp_async16_s(base + OFF_QL + so, ql + g);
    }
    CP_COMMIT();

    const int m0  = (warp >> 1) * 16;
    const int n0q = (warp & 1) * 32;
    const int n0p = (warp & 1) * 64;
    const int gr = lane >> 2, tg = lane & 3;
    const int sr = t >> 2, q4 = t & 3;

    const uint32_t a_lrow = (uint32_t)(lane & 15);
    const uint32_t a_kh   = (uint32_t)(lane >> 4) * 16;

    float oacc[8][4];
    #pragma unroll
    for (int ni = 0; ni < 8; ni++)
        #pragma unroll
        for (int e = 0; e < 4; e++) oacc[ni][e] = 0.f;
    float mval = -CUDART_INF_F, lval = 0.f;

    for (int kt = 0; kt <= qt; kt++) {
        const int k0 = kt * 64;
        __syncthreads();
        #pragma unroll
        for (int i = 0; i < 4; i++) {
            int c = t + (i << 8);
            int row = c >> 4, cc = c & 15;
            uint32_t so = (uint32_t)(row * FRB + cc * 16);
            size_t g = (size_t)(k0 + row) * DIMN + cc * 8;
            cp_async16_s(base + OFF_KH + so, kh + g);
            cp_async16_s(base + OFF_KL + so, kl + g);
            cp_async16_s(base + OFF_VH + so, vh + g);
            cp_async16_s(base + OFF_VL + so, vl + g);
        }
        CP_COMMIT();
        asm volatile("cp.async.wait_group 0;\n");
        __syncthreads();

        // ---- QK^T (3-term), K frags via x4 pair-loads ----
        float sacc[4][4];
        #pragma unroll
        for (int ni = 0; ni < 4; ni++)
            #pragma unroll
            for (int e = 0; e < 4; e++) sacc[ni][e] = 0.f;
        #pragma unroll
        for (int ks = 0; ks < 8; ks++) {
            const uint32_t kb = (uint32_t)ks * 32;
            uint32_t Bfh[4][2], Bfl[4][2];
            #pragma unroll
            for (int nj = 0; nj < 2; nj++) {
                uint32_t ro = (uint32_t)(n0q + nj * 16) + a_lrow;
                uint32_t off = ro * FRB + kb + a_kh;
                uint32_t rh[4], rl[4];
                ldsm_x4(base + OFF_KH + off, rh);
                ldsm_x4(base + OFF_KL + off, rl);
                Bfh[2*nj][0] = rh[0]; Bfh[2*nj][1] = rh[2];
                Bfh[2*nj+1][0] = rh[1]; Bfh[2*nj+1][1] = rh[3];
                Bfl[2*nj][0] = rl[0]; Bfl[2*nj][1] = rl[2];
                Bfl[2*nj+1][0] = rl[1]; Bfl[2*nj+1][1] = rl[3];
            }
            uint32_t aoff = (uint32_t)(m0 + a_lrow) * FRB + kb + a_kh;
            uint32_t Afh[4], Afl[4];
            ldsm_x4(base + OFF_QH + aoff, Afh);
            ldsm_x4(base + OFF_QL + aoff, Afl);
            #pragma unroll
            for (int ni = 0; ni < 4; ni++) {
                mma_bf16(sacc[ni], Afh, Bfh[ni]);
                mma_bf16(sacc[ni], Afl, Bfh[ni]);
                mma_bf16(sacc[ni], Afh, Bfl[ni]);
            }
        }
        #pragma unroll
        for (int ni = 0; ni < 4; ni++) {
            int cn = n0q + ni * 8 + tg * 2;
            int r0 = m0 + gr, r1 = r0 + 8;
            float s0 = sacc[ni][0] * scale, s1 = sacc[ni][1] * scale;
            float s2 = sacc[ni][2] * scale, s3 = sacc[ni][3] * scale;
            if (k0 + cn     > q0 + r0) s0 = -CUDART_INF_F;
            if (k0 + cn + 1 > q0 + r0) s1 = -CUDART_INF_F;
            if (k0 + cn     > q0 + r1) s2 = -CUDART_INF_F;
            if (k0 + cn + 1 > q0 + r1) s3 = -CUDART_INF_F;
            Ssf[r0 * SST + cn]     = s0;
            Ssf[r0 * SST + cn + 1] = s1;
            Ssf[r1 * SST + cn]     = s2;
            Ssf[r1 * SST + cn + 1] = s3;
        }
        __syncthreads();

        // ---- online softmax (quad per row), emit P bf16 hi/lo ----
        {
            float* srow = Ssf + sr * SST + q4 * 16;
            float mloc = -CUDART_INF_F;
            #pragma unroll
            for (int j = 0; j < 16; j++) mloc = fmaxf(mloc, srow[j]);
            mloc = fmaxf(mloc, __shfl_xor_sync(0xFFFFFFFFu, mloc, 1));
            mloc = fmaxf(mloc, __shfl_xor_sync(0xFFFFFFFFu, mloc, 2));
            float mnew = fmaxf(mval, mloc);
            float corr = __expf(mval - mnew);
            if (q4 == 0) scorrf[sr] = corr;
            __nv_bfloat16* php = Psh + sr * (PRB / 2) + q4 * 16;
            __nv_bfloat16* plp = Psl + sr * (PRB / 2) + q4 * 16;
            float lloc = 0.f;
            #pragma unroll
            for (int j = 0; j < 16; j++) {
                float p = __expf(srow[j] - mnew);
                __nv_bfloat16 ph = __float2bfloat16(p);
                php[j] = ph;
                plp[j] = __float2bfloat16(p - __bfloat162float(ph));
                lloc += p;
            }
            lloc += __shfl_xor_sync(0xFFFFFFFFu, lloc, 1);
            lloc += __shfl_xor_sync(0xFFFFFFFFu, lloc, 2);
            lval = lval * corr + lloc;
            mval = mnew;
        }
        __syncthreads();

        // ---- rescale, then P@V (3-term), V frags via x4.trans pair-loads ----
        {
            float c0 = scorrf[m0 + gr], c1 = scorrf[m0 + gr + 8];
            #pragma unroll
            for (int ni = 0; ni < 8; ni++) {
                oacc[ni][0] *= c0; oacc[ni][1] *= c0;
                oacc[ni][2] *= c1; oacc[ni][3] *= c1;
            }
        }
        #pragma unroll
        for (int ks = 0; ks < 4; ks++) {
            uint32_t aoff = (uint32_t)(m0 + a_lrow) * PRB + (uint32_t)ks * 32 + a_kh;
            uint32_t Afh[4], Afl[4];
            ldsm_x4(base + OFF_PH + aoff, Afh);
            ldsm_x4(base + OFF_PL + aoff, Afl);
            uint32_t vrow = (uint32_t)(ks * 16) + a_lrow;
            #pragma unroll
            for (int nj = 0; nj < 4; nj++) {
                // x4.trans: lanes 0-15 -> k rows at col group, 16-31 -> +8 cols
                uint32_t boff = vrow * FRB +
                    (uint32_t)(n0p + nj * 16 + ((lane >> 4) << 3)) * 2;
                uint32_t rh[4], rl[4];
                ldsm_x4_t(base + OFF_VH + boff, rh);
                ldsm_x4_t(base + OFF_VL + boff, rl);
                uint32_t Bfh0[2] = { rh[0], rh[1] }, Bfh1[2] = { rh[2], rh[3] };
                uint32_t Bfl0[2] = { rl[0], rl[1] }, Bfl1[2] = { rl[2], rl[3] };
                mma_bf16(oacc[2*nj],   Afh, Bfh0);
                mma_bf16(oacc[2*nj],   Afl, Bfh0);
                mma_bf16(oacc[2*nj],   Afh, Bfl0);
                mma_bf16(oacc[2*nj+1], Afh, Bfh1);
                mma_bf16(oacc[2*nj+1], Afl, Bfh1);
                mma_bf16(oacc[2*nj+1], Afh, Bfl1);
            }
        }
    }

    __syncthreads();
    if (q4 == 0) linvf[sr] = 1.f / lval;
    __syncthreads();

    const float i0v = linvf[m0 + gr], i1v = linvf[m0 + gr + 8];
    __nv_bfloat16* ath = Ath + hoff;
    __nv_bfloat16* atl = Atl + hoff;
    #pragma unroll
    for (int ni = 0; ni < 8; ni++) {
        int col = n0p + ni * 8 + tg * 2;
        split_store(ath, atl, (size_t)(q0 + m0 + gr) * DIMN + col,
                    oacc[ni][0] * i0v, oacc[ni][1] * i0v);
        split_store(ath, atl, (size_t)(q0 + m0 + gr + 8) * DIMN + col,
                    oacc[ni][2] * i1v, oacc[ni][3] * i1v);
    }
}

// ---------------------------------------------------------------------------
extern "C" void kernel_launch(void* const* d_in, const int* in_sizes, int n_in,
                              void* d_out, int out_size) {
    const float* x  = (const float*)d_in[0];
    const float* Wq = (const float*)d_in[1];
    const float* Wk = (const float*)d_in[2];
    const float* Wv = (const float*)d_in[3];
    const float* Wo = (const float*)d_in[4];
    float* out = (float*)d_out;

    __nv_bfloat16 *xh, *xl, *ath, *atl, *wth, *wtl;
    __nv_bfloat16 *qh, *ql, *kh, *kl, *vh, *vl;
    cudaGetSymbolAddress((void**)&xh,  g_xh);
    cudaGetSymbolAddress((void**)&xl,  g_xl);
    cudaGetSymbolAddress((void**)&ath, g_ath);
    cudaGetSymbolAddress((void**)&atl, g_atl);
    cudaGetSymbolAddress((void**)&wth, g_wth);
    cudaGetSymbolAddress((void**)&wtl, g_wtl);
    cudaGetSymbolAddress((void**)&qh,  g_qh);
    cudaGetSymbolAddress((void**)&ql,  g_ql);
    cudaGetSymbolAddress((void**)&kh,  g_kh);
    cudaGetSymbolAddress((void**)&kl,  g_kl);
    cudaGetSymbolAddress((void**)&vh,  g_vh);
    cudaGetSymbolAddress((void**)&vl,  g_vl);
    const size_t WSZ = (size_t)DIMN * DIMN;

    cudaFuncSetAttribute(hgemm3<0>,
                         cudaFuncAttributeMaxDynamicSharedMemorySize, GSMEM);
    cudaFuncSetAttribute(hgemm3<1>,
                         cudaFuncAttributeMaxDynamicSharedMemorySize, GSMEM);
    cudaFuncSetAttribute(flash2,
                         cudaFuncAttributeMaxDynamicSharedMemorySize, FLASH2_SMEM);

    dim3 tg(DIMN / 32, DIMN / 32), tb(32, 8);

    // idx 0-2: prep; idx 3 = hgemm3 QK (ncu capture slot)
    split_rows<<<(MTOT * DIMN) / 1024, 256>>>(x, xh, xl);
    split_transpose<<<tg, tb>>>(Wq, wth + 0 * WSZ, wtl + 0 * WSZ);
    split_transpose<<<tg, tb>>>(Wk, wth + 1 * WSZ, wtl + 1 * WSZ);

    dim3 gqk(2 * DIMN / 128, MTOT / 128);    // (32, 32): Q and K fused
    hgemm3<0><<<gqk, 512, GSMEM>>>(xh, xl, wth, wtl, nullptr,
                                   qh, ql, kh, kl, vh, vl, 0);

    split_transpose<<<tg, tb>>>(Wv, wth + 2 * WSZ, wtl + 2 * WSZ);
    dim3 gv(DIMN / 128, MTOT / 128);         // (16, 32)
    hgemm3<0><<<gv, 512, GSMEM>>>(xh, xl, wth + 2 * WSZ, wtl + 2 * WSZ, nullptr,
                                  qh, ql, kh, kl, vh, vl, 2);

    split_transpose<<<tg, tb>>>(Wo, wth + 3 * WSZ, wtl + 3 * WSZ);

    flash2<<<dim3(SS / 64, HH, BB), 256, FLASH2_SMEM>>>(qh, ql, kh, kl, vh, vl,
                                                        ath, atl);

    hgemm3<1><<<gv, 512, GSMEM>>>(ath, atl, wth + 3 * WSZ, wtl + 3 * WSZ, out,
                                  nullptr, nullptr, nullptr, nullptr,
                                  nullptr, nullptr, 0);
}

// round 11
// speedup vs baseline: 1.0292x; 1.0292x over previous
#include <cuda_runtime.h>
#include <cuda_bf16.h>
#include <math_constants.h>
#include <math.h>
#include <cstdint>

#define DIMN 2048
#define BB 2
#define SS 2048
#define HH 16
#define HDD 128
#define MTOT (BB*SS)   // 4096

// ---------------------------------------------------------------------------
// Scratch (alloc-free rule: __device__ globals)
// ---------------------------------------------------------------------------
__device__ __nv_bfloat16 g_xh[(size_t)MTOT * DIMN];
__device__ __nv_bfloat16 g_xl[(size_t)MTOT * DIMN];
__device__ __nv_bfloat16 g_ath[(size_t)MTOT * DIMN];
__device__ __nv_bfloat16 g_atl[(size_t)MTOT * DIMN];
__device__ __nv_bfloat16 g_wth[4][(size_t)DIMN * DIMN];   // W^T hi, [N][K]
__device__ __nv_bfloat16 g_wtl[4][(size_t)DIMN * DIMN];   // W^T lo
__device__ __nv_bfloat16 g_qh[(size_t)MTOT * DIMN];
__device__ __nv_bfloat16 g_ql[(size_t)MTOT * DIMN];
__device__ __nv_bfloat16 g_kh[(size_t)MTOT * DIMN];
__device__ __nv_bfloat16 g_kl[(size_t)MTOT * DIMN];
__device__ __nv_bfloat16 g_vh[(size_t)MTOT * DIMN];
__device__ __nv_bfloat16 g_vl[(size_t)MTOT * DIMN];
__device__ float2 g_rope[(size_t)SS * 64];                // (cos, sin) per (s, dp)

// ---------------------------------------------------------------------------
// PTX helpers (generic sm_80+ features only)
// ---------------------------------------------------------------------------
__device__ __forceinline__ void cp_async16_s(uint32_t s, const void* g) {
    asm volatile("cp.async.cg.shared.global [%0], [%1], 16;\n" :: "r"(s), "l"(g));
}
#define CP_COMMIT() asm volatile("cp.async.commit_group;\n")

__device__ __forceinline__ uint32_t smem_u32(const void* p) {
    uint32_t a;
    asm("{ .reg .u64 t; cvta.to.shared.u64 t, %1; cvt.u32.u64 %0, t; }"
        : "=r"(a) : "l"(p));
    return a;
}

__device__ __forceinline__ void ldsm_x4(uint32_t addr, uint32_t* r) {
    asm volatile("ldmatrix.sync.aligned.m8n8.x4.shared.b16 {%0,%1,%2,%3}, [%4];"
                 : "=r"(r[0]), "=r"(r[1]), "=r"(r[2]), "=r"(r[3]) : "r"(addr));
}
__device__ __forceinline__ void ldsm_x4_t(uint32_t addr, uint32_t* r) {
    asm volatile("ldmatrix.sync.aligned.m8n8.x4.trans.shared.b16 {%0,%1,%2,%3}, [%4];"
                 : "=r"(r[0]), "=r"(r[1]), "=r"(r[2]), "=r"(r[3]) : "r"(addr));
}

__device__ __forceinline__ void mma_bf16(float* d, const uint32_t* a,
                                         const uint32_t* b) {
    asm volatile(
        "mma.sync.aligned.m16n8k16.row.col.f32.bf16.bf16.f32 "
        "{%0,%1,%2,%3}, {%4,%5,%6,%7}, {%8,%9}, {%0,%1,%2,%3};"
        : "+f"(d[0]), "+f"(d[1]), "+f"(d[2]), "+f"(d[3])
        : "r"(a[0]), "r"(a[1]), "r"(a[2]), "r"(a[3]), "r"(b[0]), "r"(b[1]));
}

__device__ __forceinline__ void split_store(__nv_bfloat16* h, __nv_bfloat16* l,
                                            size_t off, float v0, float v1) {
    __nv_bfloat16 h0 = __float2bfloat16(v0), h1 = __float2bfloat16(v1);
    *(__nv_bfloat162*)(h + off) = __nv_bfloat162(h0, h1);
    *(__nv_bfloat162*)(l + off) = __nv_bfloat162(
        __float2bfloat16(v0 - __bfloat162float(h0)),
        __float2bfloat16(v1 - __bfloat162float(h1)));
}

// ---------------------------------------------------------------------------
// Prep: split fp32 rows into bf16 hi/lo
// ---------------------------------------------------------------------------
__global__ void split_rows(const float* __restrict__ in,
                           __nv_bfloat16* __restrict__ h,
                           __nv_bfloat16* __restrict__ l) {
    size_t i = ((size_t)blockIdx.x * 256 + threadIdx.x) * 4;
    float4 v = *(const float4*)(in + i);
    __nv_bfloat16 h0 = __float2bfloat16(v.x), h1 = __float2bfloat16(v.y);
    __nv_bfloat16 h2 = __float2bfloat16(v.z), h3 = __float2bfloat16(v.w);
    *(__nv_bfloat162*)(h + i)     = __nv_bfloat162(h0, h1);
    *(__nv_bfloat162*)(h + i + 2) = __nv_bfloat162(h2, h3);
    *(__nv_bfloat162*)(l + i) = __nv_bfloat162(
        __float2bfloat16(v.x - __bfloat162float(h0)),
        __float2bfloat16(v.y - __bfloat162float(h1)));
    *(__nv_bfloat162*)(l + i + 2) = __nv_bfloat162(
        __float2bfloat16(v.z - __bfloat162float(h2)),
        __float2bfloat16(v.w - __bfloat162float(h3)));
}

// ---------------------------------------------------------------------------
// Prep: transpose all 4 weights (blockIdx.z selects) -> W^T hi/lo
// ---------------------------------------------------------------------------
__global__ void split_transpose_all(const float* __restrict__ W0,
                                    const float* __restrict__ W1,
                                    const float* __restrict__ W2,
                                    const float* __restrict__ W3,
                                    __nv_bfloat16* __restrict__ th,
                                    __nv_bfloat16* __restrict__ tl) {
    __shared__ float ts[32][33];
    const float* W = (blockIdx.z == 0) ? W0 : (blockIdx.z == 1) ? W1
                   : (blockIdx.z == 2) ? W2 : W3;
    const size_t mo = (size_t)blockIdx.z * DIMN * DIMN;
    const int bx = blockIdx.x * 32, by = blockIdx.y * 32;
    const int tx = threadIdx.x, ty = threadIdx.y;   // 32 x 8
    #pragma unroll
    for (int j = 0; j < 4; j++)
        ts[ty + 8 * j][tx] = W[(size_t)(by + ty + 8 * j) * DIMN + bx + tx];
    __syncthreads();
    #pragma unroll
    for (int j = 0; j < 4; j++) {
        float v = ts[tx][ty + 8 * j];
        __nv_bfloat16 h = __float2bfloat16(v);
        __nv_bfloat16 l = __float2bfloat16(v - __bfloat162float(h));
        size_t o = mo + (size_t)(bx + ty + 8 * j) * DIMN + by + tx;
        th[o] = h;
        tl[o] = l;
    }
}

// ---------------------------------------------------------------------------
// Prep: RoPE cos/sin table  g_rope[s][dp]
// ---------------------------------------------------------------------------
__global__ void rope_table() {
    int idx = blockIdx.x * 256 + threadIdx.x;    // 0 .. SS*64-1
    int s = idx >> 6, dp = idx & 63;
    float inv = powf(10000.0f, -(float)dp * (1.0f / 64.0f));
    float sn, cs;
    sincosf((float)s * inv, &sn, &cs);
    g_rope[idx] = make_float2(cs, sn);
}

// ---------------------------------------------------------------------------
// bf16 3-term split GEMM, block tile 128x256, BK=32, 512 threads (16 warps,
// warp tile 32x64), 3-stage cp.async.
// MODE 0: QKV epilogue — RoPE (mats 0,1) via table, emit bf16 hi/lo.
// MODE 1: plain fp32 epilogue to C.
// ---------------------------------------------------------------------------
#define ROWB 80
#define A_BYTES (128 * ROWB)            // 10240
#define B_BYTES (256 * ROWB)            // 20480
#define STG_BYTES (2 * A_BYTES + 2 * B_BYTES)   // 61440
#define NSTAGE 3
#define GSMEM (NSTAGE * STG_BYTES)      // 184320

__device__ __forceinline__ void fill_stage(uint32_t stg,
        const __nv_bfloat16* ah, const __nv_bfloat16* al,
        const __nv_bfloat16* bh, const __nv_bfloat16* bl,
        int k0, int t) {
    // A: 512 chunks (128 rows x 4), one per thread, both arrays
    {
        int row = t >> 2, cc = t & 3;
        uint32_t so = (uint32_t)(row * ROWB + cc * 16);
        size_t g = (size_t)row * DIMN + k0 + cc * 8;
        cp_async16_s(stg + so,           ah + g);
        cp_async16_s(stg + A_BYTES + so, al + g);
    }
    // B: 1024 chunks (256 rows x 4), two per thread, both arrays
    #pragma unroll
    for (int i = 0; i < 2; i++) {
        int c = t + (i << 9);
        int row = c >> 2, cc = c & 3;
        uint32_t so = (uint32_t)(row * ROWB + cc * 16);
        size_t g = (size_t)row * DIMN + k0 + cc * 8;
        cp_async16_s(stg + 2 * A_BYTES + so,           bh + g);
        cp_async16_s(stg + 2 * A_BYTES + B_BYTES + so, bl + g);
    }
}

template <int MODE>
__global__ __launch_bounds__(512)
void hgemm3(const __nv_bfloat16* __restrict__ Ah, const __nv_bfloat16* __restrict__ Al,
            const __nv_bfloat16* __restrict__ Bh, const __nv_bfloat16* __restrict__ Bl,
            float* __restrict__ C,
            __nv_bfloat16* __restrict__ qh, __nv_bfloat16* __restrict__ ql,
            __nv_bfloat16* __restrict__ kh, __nv_bfloat16* __restrict__ kl,
            __nv_bfloat16* __restrict__ vh, __nv_bfloat16* __restrict__ vl) {
    extern __shared__ char dsm[];
    const uint32_t base = smem_u32(dsm);

    const int t    = threadIdx.x;
    const int lane = t & 31;
    const int warp = t >> 5;              // 0..15
    const int wm   = warp & 3;            // m offset 32*wm
    const int wn   = warp >> 2;           // n offset 64*wn
    const int bm   = blockIdx.y << 7;
    const int bn   = blockIdx.x << 8;     // 256-wide tiles

    const __nv_bfloat16* ah0 = Ah + (size_t)bm * DIMN;
    const __nv_bfloat16* al0 = Al + (size_t)bm * DIMN;
    const __nv_bfloat16* bh0 = Bh + (size_t)bn * DIMN;
    const __nv_bfloat16* bl0 = Bl + (size_t)bn * DIMN;

    const int nloc = bn & 2047;

    float acc[2][8][4];
    #pragma unroll
    for (int mi = 0; mi < 2; mi++)
        #pragma unroll
        for (int ni = 0; ni < 8; ni++)
            #pragma unroll
            for (int e = 0; e < 4; e++) acc[mi][ni][e] = 0.f;

    const uint32_t a_lrow  = (uint32_t)(lane & 15);
    const uint32_t a_khalf = (uint32_t)(lane >> 4) * 16;

    fill_stage(base, ah0, al0, bh0, bl0, 0, t);
    CP_COMMIT();
    fill_stage(base + STG_BYTES, ah0, al0, bh0, bl0, 32, t);
    CP_COMMIT();

    const int NT = DIMN / 32;   // 64
    uint32_t sidx = 0, fidx = 2;
    for (int kt = 0; kt < NT; kt++) {
        if (kt + 2 < NT) {
            fill_stage(base + fidx * STG_BYTES, ah0, al0, bh0, bl0,
                       (kt + 2) * 32, t);
            CP_COMMIT();
            asm volatile("cp.async.wait_group 2;\n");
        } else {
            asm volatile("cp.async.wait_group 0;\n");
        }
        __syncthreads();

        const uint32_t stg  = base + sidx * STG_BYTES;
        const uint32_t As_h = stg;
        const uint32_t As_l = stg + A_BYTES;
        const uint32_t Bs_h = stg + 2 * A_BYTES;
        const uint32_t Bs_l = stg + 2 * A_BYTES + B_BYTES;

        #pragma unroll
        for (int ks = 0; ks < 2; ks++) {
            const uint32_t kb = (uint32_t)ks * 32;
            uint32_t Afh[2][4], Afl[2][4];
            #pragma unroll
            for (int mi = 0; mi < 2; mi++) {
                uint32_t ro = (uint32_t)(wm * 32 + mi * 16) + a_lrow;
                uint32_t off = ro * ROWB + kb + a_khalf;
                ldsm_x4(As_h + off, Afh[mi]);
                ldsm_x4(As_l + off, Afl[mi]);
            }
            #pragma unroll
            for (int nj = 0; nj < 4; nj++) {
                uint32_t ro = (uint32_t)(wn * 64 + nj * 16) + a_lrow;
                uint32_t off = ro * ROWB + kb + a_khalf;
                uint32_t rh[4], rl[4];
                ldsm_x4(Bs_h + off, rh);
                ldsm_x4(Bs_l + off, rl);
                uint32_t Bh0[2] = { rh[0], rh[2] }, Bh1[2] = { rh[1], rh[3] };
                uint32_t Bl0[2] = { rl[0], rl[2] }, Bl1[2] = { rl[1], rl[3] };
                #pragma unroll
                for (int mi = 0; mi < 2; mi++) {
                    mma_bf16(acc[mi][2*nj],   Afh[mi], Bh0);
                    mma_bf16(acc[mi][2*nj],   Afl[mi], Bh0);
                    mma_bf16(acc[mi][2*nj],   Afh[mi], Bl0);
                    mma_bf16(acc[mi][2*nj+1], Afh[mi], Bh1);
                    mma_bf16(acc[mi][2*nj+1], Afl[mi], Bh1);
                    mma_bf16(acc[mi][2*nj+1], Afh[mi], Bl1);
                }
            }
        }
        __syncthreads();

        sidx = (sidx + 1 == NSTAGE) ? 0 : sidx + 1;
        fidx = (fidx + 1 == NSTAGE) ? 0 : fidx + 1;
    }

    const int gr = lane >> 2, tg = lane & 3;
    if (MODE == 1) {
        #pragma unroll
        for (int mi = 0; mi < 2; mi++) {
            #pragma unroll
            for (int ni = 0; ni < 8; ni++) {
                const int m = bm + wm * 32 + mi * 16 + gr;
                const int n = nloc + wn * 64 + ni * 8 + tg * 2;
                *(float2*)(C + (size_t)m * DIMN + n) =
                    make_float2(acc[mi][ni][0], acc[mi][ni][1]);
                *(float2*)(C + (size_t)(m + 8) * DIMN + n) =
                    make_float2(acc[mi][ni][2], acc[mi][ni][3]);
            }
        }
    } else {
        const int gm = bn >> 11;                 // 0=q, 1=k, 2=v
        __nv_bfloat16 *oh, *ol;
        if (gm == 0)      { oh = qh; ol = ql; }
        else if (gm == 1) { oh = kh; ol = kl; }
        else              { oh = vh; ol = vl; }
        const bool dorope = (gm < 2);
        #pragma unroll
        for (int mi = 0; mi < 2; mi++) {
            #pragma unroll
            for (int ni = 0; ni < 8; ni++) {
                const int n  = nloc + wn * 64 + ni * 8 + tg * 2;
                const int r0 = bm + wm * 32 + mi * 16 + gr;
                float v0 = acc[mi][ni][0], v1 = acc[mi][ni][1];
                float v2 = acc[mi][ni][2], v3 = acc[mi][ni][3];
                if (dorope) {
                    int dp = (n >> 1) & 63;
                    float2 c0 = g_rope[(size_t)(r0 & (SS - 1)) * 64 + dp];
                    float2 c1 = g_rope[(size_t)((r0 + 8) & (SS - 1)) * 64 + dp];
                    float t0 = v0 * c0.x - v1 * c0.y, t1 = v0 * c0.y + v1 * c0.x;
                    v0 = t0; v1 = t1;
                    float t2 = v2 * c1.x - v3 * c1.y, t3 = v2 * c1.y + v3 * c1.x;
                    v2 = t2; v3 = t3;
                }
                split_store(oh, ol, (size_t)r0 * DIMN + n, v0, v1);
                split_store(oh, ol, (size_t)(r0 + 8) * DIMN + n, v2, v3);
            }
        }
    }
}

// ---------------------------------------------------------------------------
// flash2: tensor-core causal flash attention, BM=BN=64, 256 threads.
// Emits output directly as bf16 hi/lo (ath/atl) for the O-projection.
// ---------------------------------------------------------------------------
#define FRB 272                 // Q/K/V smem row bytes (128 bf16 + 8 pad)
#define PRB 144                 // P smem row bytes (64 bf16 + 8 pad)
#define SST 66                  // Ss fp32 stride
#define OFF_QH 0
#define OFF_QL 17408
#define OFF_KH 34816
#define OFF_KL 52224
#define OFF_VH 69632
#define OFF_VL 87040
#define OFF_SSX 104448
#define OFF_PH 121344
#define OFF_PL 130560
#define OFF_CORR 139776
#define OFF_LINV 140032
#define FLASH2_SMEM 140288

__global__ __launch_bounds__(256, 1)
void flash2(const __nv_bfloat16* __restrict__ Qh, const __nv_bfloat16* __restrict__ Ql,
            const __nv_bfloat16* __restrict__ Kh, const __nv_bfloat16* __restrict__ Kl,
            const __nv_bfloat16* __restrict__ Vh, const __nv_bfloat16* __restrict__ Vl,
            __nv_bfloat16* __restrict__ Ath, __nv_bfloat16* __restrict__ Atl) {
    extern __shared__ char fsm[];
    const uint32_t base = smem_u32(fsm);
    float* Ssf    = (float*)(fsm + OFF_SSX);
    float* scorrf = (float*)(fsm + OFF_CORR);
    float* linvf  = (float*)(fsm + OFF_LINV);
    __nv_bfloat16* Psh = (__nv_bfloat16*)(fsm + OFF_PH);
    __nv_bfloat16* Psl = (__nv_bfloat16*)(fsm + OFF_PL);

    const int t = threadIdx.x, lane = t & 31, warp = t >> 5;
    const int qt = blockIdx.x, h = blockIdx.y, b = blockIdx.z;
    const int q0 = qt * 64;
    const float scale = 0.08838834764831845f;   // 1/sqrt(128)

    const size_t hoff = ((size_t)b * SS) * DIMN + (size_t)h * HDD;
    const __nv_bfloat16* qh = Qh + hoff;
    const __nv_bfloat16* ql = Ql + hoff;
    const __nv_bfloat16* kh = Kh + hoff;
    const __nv_bfloat16* kl = Kl + hoff;
    const __nv_bfloat16* vh = Vh + hoff;
    const __nv_bfloat16* vl = Vl + hoff;

    #pragma unroll
    for (int i = 0; i < 4; i++) {
        int c = t + (i << 8);
        int row = c >> 4, cc = c & 15;
        uint32_t so = (uint32_t)(row * FRB + cc * 16);
        size_t g = (size_t)(q0 + row) * DIMN + cc * 8;
        cp_async16_s(base + OFF_QH + so, qh + g);
        cp_async16_s(base + OFF_QL + so, ql + g);
    }
    CP_COMMIT();

    const int m0  = (warp >> 1) * 16;
    const int n0q = (warp & 1) * 32;
    const int n0p = (warp & 1) * 64;
    const int gr = lane >> 2, tg = lane & 3;
    const int sr = t >> 2, q4 = t & 3;

    const uint32_t a_lrow = (uint32_t)(lane & 15);
    const uint32_t a_kh   = (uint32_t)(lane >> 4) * 16;

    float oacc[8][4];
    #pragma unroll
    for (int ni = 0; ni < 8; ni++)
        #pragma unroll
        for (int e = 0; e < 4; e++) oacc[ni][e] = 0.f;
    float mval = -CUDART_INF_F, lval = 0.f;

    for (int kt = 0; kt <= qt; kt++) {
        const int k0 = kt * 64;
        __syncthreads();
        #pragma unroll
        for (int i = 0; i < 4; i++) {
            int c = t + (i << 8);
            int row = c >> 4, cc = c & 15;
            uint32_t so = (uint32_t)(row * FRB + cc * 16);
            size_t g = (size_t)(k0 + row) * DIMN + cc * 8;
            cp_async16_s(base + OFF_KH + so, kh + g);
            cp_async16_s(base + OFF_KL + so, kl + g);
            cp_async16_s(base + OFF_VH + so, vh + g);
            cp_async16_s(base + OFF_VL + so, vl + g);
        }
        CP_COMMIT();
        asm volatile("cp.async.wait_group 0;\n");
        __syncthreads();

        // ---- QK^T (3-term), K frags via x4 pair-loads ----
        float sacc[4][4];
        #pragma unroll
        for (int ni = 0; ni < 4; ni++)
            #pragma unroll
            for (int e = 0; e < 4; e++) sacc[ni][e] = 0.f;
        #pragma unroll
        for (int ks = 0; ks < 8; ks++) {
            const uint32_t kb = (uint32_t)ks * 32;
            uint32_t Bfh[4][2], Bfl[4][2];
            #pragma unroll
            for (int nj = 0; nj < 2; nj++) {
                uint32_t ro = (uint32_t)(n0q + nj * 16) + a_lrow;
                uint32_t off = ro * FRB + kb + a_kh;
                uint32_t rh[4], rl[4];
                ldsm_x4(base + OFF_KH + off, rh);
                ldsm_x4(base + OFF_KL + off, rl);
                Bfh[2*nj][0] = rh[0]; Bfh[2*nj][1] = rh[2];
                Bfh[2*nj+1][0] = rh[1]; Bfh[2*nj+1][1] = rh[3];
                Bfl[2*nj][0] = rl[0]; Bfl[2*nj][1] = rl[2];
                Bfl[2*nj+1][0] = rl[1]; Bfl[2*nj+1][1] = rl[3];
            }
            uint32_t aoff = (uint32_t)(m0 + a_lrow) * FRB + kb + a_kh;
            uint32_t Afh[4], Afl[4];
            ldsm_x4(base + OFF_QH + aoff, Afh);
            ldsm_x4(base + OFF_QL + aoff, Afl);
            #pragma unroll
            for (int ni = 0; ni < 4; ni++) {
                mma_bf16(sacc[ni], Afh, Bfh[ni]);
                mma_bf16(sacc[ni], Afl, Bfh[ni]);
                mma_bf16(sacc[ni], Afh, Bfl[ni]);
            }
        }
        #pragma unroll
        for (int ni = 0; ni < 4; ni++) {
            int cn = n0q + ni * 8 + tg * 2;
            int r0 = m0 + gr, r1 = r0 + 8;
            float s0 = sacc[ni][0] * scale, s1 = sacc[ni][1] * scale;
            float s2 = sacc[ni][2] * scale, s3 = sacc[ni][3] * scale;
            if (k0 + cn     > q0 + r0) s0 = -CUDART_INF_F;
            if (k0 + cn + 1 > q0 + r0) s1 = -CUDART_INF_F;
            if (k0 + cn     > q0 + r1) s2 = -CUDART_INF_F;
            if (k0 + cn + 1 > q0 + r1) s3 = -CUDART_INF_F;
            Ssf[r0 * SST + cn]     = s0;
            Ssf[r0 * SST + cn + 1] = s1;
            Ssf[r1 * SST + cn]     = s2;
            Ssf[r1 * SST + cn + 1] = s3;
        }
        __syncthreads();

        // ---- online softmax (quad per row), emit P bf16 hi/lo ----
        {
            float* srow = Ssf + sr * SST + q4 * 16;
            float mloc = -CUDART_INF_F;
            #pragma unroll
            for (int j = 0; j < 16; j++) mloc = fmaxf(mloc, srow[j]);
            mloc = fmaxf(mloc, __shfl_xor_sync(0xFFFFFFFFu, mloc, 1));
            mloc = fmaxf(mloc, __shfl_xor_sync(0xFFFFFFFFu, mloc, 2));
            float mnew = fmaxf(mval, mloc);
            float corr = __expf(mval - mnew);
            if (q4 == 0) scorrf[sr] = corr;
            __nv_bfloat16* php = Psh + sr * (PRB / 2) + q4 * 16;
            __nv_bfloat16* plp = Psl + sr * (PRB / 2) + q4 * 16;
            float lloc = 0.f;
            #pragma unroll
            for (int j = 0; j < 16; j++) {
                float p = __expf(srow[j] - mnew);
                __nv_bfloat16 ph = __float2bfloat16(p);
                php[j] = ph;
                plp[j] = __float2bfloat16(p - __bfloat162float(ph));
                lloc += p;
            }
            lloc += __shfl_xor_sync(0xFFFFFFFFu, lloc, 1);
            lloc += __shfl_xor_sync(0xFFFFFFFFu, lloc, 2);
            lval = lval * corr + lloc;
            mval = mnew;
        }
        __syncthreads();

        // ---- rescale, then P@V (3-term), V frags via x4.trans pair-loads ----
        {
            float c0 = scorrf[m0 + gr], c1 = scorrf[m0 + gr + 8];
            #pragma unroll
            for (int ni = 0; ni < 8; ni++) {
                oacc[ni][0] *= c0; oacc[ni][1] *= c0;
                oacc[ni][2] *= c1; oacc[ni][3] *= c1;
            }
        }
        #pragma unroll
        for (int ks = 0; ks < 4; ks++) {
            uint32_t aoff = (uint32_t)(m0 + a_lrow) * PRB + (uint32_t)ks * 32 + a_kh;
            uint32_t Afh[4], Afl[4];
            ldsm_x4(base + OFF_PH + aoff, Afh);
            ldsm_x4(base + OFF_PL + aoff, Afl);
            uint32_t vrow = (uint32_t)(ks * 16) + a_lrow;
            #pragma unroll
            for (int nj = 0; nj < 4; nj++) {
                uint32_t boff = vrow * FRB +
                    (uint32_t)(n0p + nj * 16 + ((lane >> 4) << 3)) * 2;
                uint32_t rh[4], rl[4];
                ldsm_x4_t(base + OFF_VH + boff, rh);
                ldsm_x4_t(base + OFF_VL + boff, rl);
                uint32_t Bfh0[2] = { rh[0], rh[1] }, Bfh1[2] = { rh[2], rh[3] };
                uint32_t Bfl0[2] = { rl[0], rl[1] }, Bfl1[2] = { rl[2], rl[3] };
                mma_bf16(oacc[2*nj],   Afh, Bfh0);
                mma_bf16(oacc[2*nj],   Afl, Bfh0);
                mma_bf16(oacc[2*nj],   Afh, Bfl0);
                mma_bf16(oacc[2*nj+1], Afh, Bfh1);
                mma_bf16(oacc[2*nj+1], Afl, Bfh1);
                mma_bf16(oacc[2*nj+1], Afh, Bfl1);
            }
        }
    }

    __syncthreads();
    if (q4 == 0) linvf[sr] = 1.f / lval;
    __syncthreads();

    const float i0v = linvf[m0 + gr], i1v = linvf[m0 + gr + 8];
    __nv_bfloat16* ath = Ath + hoff;
    __nv_bfloat16* atl = Atl + hoff;
    #pragma unroll
    for (int ni = 0; ni < 8; ni++) {
        int col = n0p + ni * 8 + tg * 2;
        split_store(ath, atl, (size_t)(q0 + m0 + gr) * DIMN + col,
                    oacc[ni][0] * i0v, oacc[ni][1] * i0v);
        split_store(ath, atl, (size_t)(q0 + m0 + gr + 8) * DIMN + col,
                    oacc[ni][2] * i1v, oacc[ni][3] * i1v);
    }
}

// ---------------------------------------------------------------------------
extern "C" void kernel_launch(void* const* d_in, const int* in_sizes, int n_in,
                              void* d_out, int out_size) {
    const float* x  = (const float*)d_in[0];
    const float* Wq = (const float*)d_in[1];
    const float* Wk = (const float*)d_in[2];
    const float* Wv = (const float*)d_in[3];
    const float* Wo = (const float*)d_in[4];
    float* out = (float*)d_out;

    __nv_bfloat16 *xh, *xl, *ath, *atl, *wth, *wtl;
    __nv_bfloat16 *qh, *ql, *kh, *kl, *vh, *vl;
    cudaGetSymbolAddress((void**)&xh,  g_xh);
    cudaGetSymbolAddress((void**)&xl,  g_xl);
    cudaGetSymbolAddress((void**)&ath, g_ath);
    cudaGetSymbolAddress((void**)&atl, g_atl);
    cudaGetSymbolAddress((void**)&wth, g_wth);
    cudaGetSymbolAddress((void**)&wtl, g_wtl);
    cudaGetSymbolAddress((void**)&qh,  g_qh);
    cudaGetSymbolAddress((void**)&ql,  g_ql);
    cudaGetSymbolAddress((void**)&kh,  g_kh);
    cudaGetSymbolAddress((void**)&kl,  g_kl);
    cudaGetSymbolAddress((void**)&vh,  g_vh);
    cudaGetSymbolAddress((void**)&vl,  g_vl);
    const size_t WSZ = (size_t)DIMN * DIMN;

    cudaFuncSetAttribute(hgemm3<0>,
                         cudaFuncAttributeMaxDynamicSharedMemorySize, GSMEM);
    cudaFuncSetAttribute(hgemm3<1>,
                         cudaFuncAttributeMaxDynamicSharedMemorySize, GSMEM);
    cudaFuncSetAttribute(flash2,
                         cudaFuncAttributeMaxDynamicSharedMemorySize, FLASH2_SMEM);

    // idx 0-2: prep; idx 3 = fused QKV GEMM (ncu capture slot)
    split_rows<<<(MTOT * DIMN) / 1024, 256>>>(x, xh, xl);
    dim3 tga(DIMN / 32, DIMN / 32, 4), tb(32, 8);
    split_transpose_all<<<tga, tb>>>(Wq, Wk, Wv, Wo, wth, wtl);
    rope_table<<<(SS * 64) / 256, 256>>>();

    dim3 gqkv(3 * DIMN / 256, MTOT / 128);   // (24, 32)
    hgemm3<0><<<gqkv, 512, GSMEM>>>(xh, xl, wth, wtl, nullptr,
                                    qh, ql, kh, kl, vh, vl);

    flash2<<<dim3(SS / 64, HH, BB), 256, FLASH2_SMEM>>>(qh, ql, kh, kl, vh, vl,
                                                        ath, atl);

    dim3 go(DIMN / 256, MTOT / 128);         // (8, 32)
    hgemm3<1><<<go, 512, GSMEM>>>(ath, atl, wth + 3 * WSZ, wtl + 3 * WSZ, out,
                                  nullptr, nullptr, nullptr, nullptr,
                                  nullptr, nullptr);
}

// round 12
// speedup vs baseline: 1.0345x; 1.0052x over previous
#include <cuda_runtime.h>
#include <cuda_bf16.h>
#include <math_constants.h>
#include <math.h>
#include <cstdint>

#define DIMN 2048
#define BB 2
#define SS 2048
#define HH 16
#define HDD 128
#define MTOT (BB*SS)   // 4096

// ---------------------------------------------------------------------------
// Scratch (alloc-free rule: __device__ globals)
// ---------------------------------------------------------------------------
__device__ __nv_bfloat16 g_xh[(size_t)MTOT * DIMN];
__device__ __nv_bfloat16 g_xl[(size_t)MTOT * DIMN];
__device__ __nv_bfloat16 g_ath[(size_t)MTOT * DIMN];
__device__ __nv_bfloat16 g_atl[(size_t)MTOT * DIMN];
__device__ __nv_bfloat16 g_wth[4][(size_t)DIMN * DIMN];   // W^T hi, [N][K]
__device__ __nv_bfloat16 g_wtl[4][(size_t)DIMN * DIMN];   // W^T lo
__device__ __nv_bfloat16 g_qh[(size_t)MTOT * DIMN];
__device__ __nv_bfloat16 g_ql[(size_t)MTOT * DIMN];
__device__ __nv_bfloat16 g_kh[(size_t)MTOT * DIMN];
__device__ __nv_bfloat16 g_kl[(size_t)MTOT * DIMN];
__device__ __nv_bfloat16 g_vh[(size_t)MTOT * DIMN];
__device__ __nv_bfloat16 g_vl[(size_t)MTOT * DIMN];
__device__ float2 g_rope[(size_t)SS * 64];                // (cos, sin) per (s, dp)

// ---------------------------------------------------------------------------
// PTX helpers (generic sm_80+ features only)
// ---------------------------------------------------------------------------
__device__ __forceinline__ void cp_async16_s(uint32_t s, const void* g) {
    asm volatile("cp.async.cg.shared.global [%0], [%1], 16;\n" :: "r"(s), "l"(g));
}
#define CP_COMMIT() asm volatile("cp.async.commit_group;\n")

__device__ __forceinline__ uint32_t smem_u32(const void* p) {
    uint32_t a;
    asm("{ .reg .u64 t; cvta.to.shared.u64 t, %1; cvt.u32.u64 %0, t; }"
        : "=r"(a) : "l"(p));
    return a;
}

__device__ __forceinline__ void ldsm_x4(uint32_t addr, uint32_t* r) {
    asm volatile("ldmatrix.sync.aligned.m8n8.x4.shared.b16 {%0,%1,%2,%3}, [%4];"
                 : "=r"(r[0]), "=r"(r[1]), "=r"(r[2]), "=r"(r[3]) : "r"(addr));
}
__device__ __forceinline__ void ldsm_x4_t(uint32_t addr, uint32_t* r) {
    asm volatile("ldmatrix.sync.aligned.m8n8.x4.trans.shared.b16 {%0,%1,%2,%3}, [%4];"
                 : "=r"(r[0]), "=r"(r[1]), "=r"(r[2]), "=r"(r[3]) : "r"(addr));
}

__device__ __forceinline__ void mma_bf16(float* d, const uint32_t* a,
                                         const uint32_t* b) {
    asm volatile(
        "mma.sync.aligned.m16n8k16.row.col.f32.bf16.bf16.f32 "
        "{%0,%1,%2,%3}, {%4,%5,%6,%7}, {%8,%9}, {%0,%1,%2,%3};"
        : "+f"(d[0]), "+f"(d[1]), "+f"(d[2]), "+f"(d[3])
        : "r"(a[0]), "r"(a[1]), "r"(a[2]), "r"(a[3]), "r"(b[0]), "r"(b[1]));
}

__device__ __forceinline__ void mma_bf16_2(float* d, const uint32_t* a,
                                           uint32_t b0, uint32_t b1) {
    asm volatile(
        "mma.sync.aligned.m16n8k16.row.col.f32.bf16.bf16.f32 "
        "{%0,%1,%2,%3}, {%4,%5,%6,%7}, {%8,%9}, {%0,%1,%2,%3};"
        : "+f"(d[0]), "+f"(d[1]), "+f"(d[2]), "+f"(d[3])
        : "r"(a[0]), "r"(a[1]), "r"(a[2]), "r"(a[3]), "r"(b0), "r"(b1));
}

__device__ __forceinline__ void split_store(__nv_bfloat16* h, __nv_bfloat16* l,
                                            size_t off, float v0, float v1) {
    __nv_bfloat16 h0 = __float2bfloat16(v0), h1 = __float2bfloat16(v1);
    *(__nv_bfloat162*)(h + off) = __nv_bfloat162(h0, h1);
    *(__nv_bfloat162*)(l + off) = __nv_bfloat162(
        __float2bfloat16(v0 - __bfloat162float(h0)),
        __float2bfloat16(v1 - __bfloat162float(h1)));
}

// ---------------------------------------------------------------------------
// Prep: split fp32 rows into bf16 hi/lo
// ---------------------------------------------------------------------------
__global__ void split_rows(const float* __restrict__ in,
                           __nv_bfloat16* __restrict__ h,
                           __nv_bfloat16* __restrict__ l) {
    size_t i = ((size_t)blockIdx.x * 256 + threadIdx.x) * 4;
    float4 v = *(const float4*)(in + i);
    __nv_bfloat16 h0 = __float2bfloat16(v.x), h1 = __float2bfloat16(v.y);
    __nv_bfloat16 h2 = __float2bfloat16(v.z), h3 = __float2bfloat16(v.w);
    *(__nv_bfloat162*)(h + i)     = __nv_bfloat162(h0, h1);
    *(__nv_bfloat162*)(h + i + 2) = __nv_bfloat162(h2, h3);
    *(__nv_bfloat162*)(l + i) = __nv_bfloat162(
        __float2bfloat16(v.x - __bfloat162float(h0)),
        __float2bfloat16(v.y - __bfloat162float(h1)));
    *(__nv_bfloat162*)(l + i + 2) = __nv_bfloat162(
        __float2bfloat16(v.z - __bfloat162float(h2)),
        __float2bfloat16(v.w - __bfloat162float(h3)));
}

// ---------------------------------------------------------------------------
// Prep: transpose all 4 weights (blockIdx.z selects) -> W^T hi/lo
// ---------------------------------------------------------------------------
__global__ void split_transpose_all(const float* __restrict__ W0,
                                    const float* __restrict__ W1,
                                    const float* __restrict__ W2,
                                    const float* __restrict__ W3,
                                    __nv_bfloat16* __restrict__ th,
                                    __nv_bfloat16* __restrict__ tl) {
    __shared__ float ts[32][33];
    const float* W = (blockIdx.z == 0) ? W0 : (blockIdx.z == 1) ? W1
                   : (blockIdx.z == 2) ? W2 : W3;
    const size_t mo = (size_t)blockIdx.z * DIMN * DIMN;
    const int bx = blockIdx.x * 32, by = blockIdx.y * 32;
    const int tx = threadIdx.x, ty = threadIdx.y;   // 32 x 8
    #pragma unroll
    for (int j = 0; j < 4; j++)
        ts[ty + 8 * j][tx] = W[(size_t)(by + ty + 8 * j) * DIMN + bx + tx];
    __syncthreads();
    #pragma unroll
    for (int j = 0; j < 4; j++) {
        float v = ts[tx][ty + 8 * j];
        __nv_bfloat16 h = __float2bfloat16(v);
        __nv_bfloat16 l = __float2bfloat16(v - __bfloat162float(h));
        size_t o = mo + (size_t)(bx + ty + 8 * j) * DIMN + by + tx;
        th[o] = h;
        tl[o] = l;
    }
}

// ---------------------------------------------------------------------------
// Prep: RoPE cos/sin table  g_rope[s][dp]
// ---------------------------------------------------------------------------
__global__ void rope_table() {
    int idx = blockIdx.x * 256 + threadIdx.x;    // 0 .. SS*64-1
    int s = idx >> 6, dp = idx & 63;
    float inv = powf(10000.0f, -(float)dp * (1.0f / 64.0f));
    float sn, cs;
    sincosf((float)s * inv, &sn, &cs);
    g_rope[idx] = make_float2(cs, sn);
}

// ---------------------------------------------------------------------------
// bf16 3-term split GEMM, block tile 128x256, BK=32, 512 threads (16 warps,
// warp tile 32x64), 3-stage cp.async. Term-grouped mma ordering: same-acc
// reuse distance = 4 independent HMMAs (hides fixed HMMA latency).
// MODE 0: QKV epilogue — RoPE (mats 0,1) via table, emit bf16 hi/lo.
// MODE 1: plain fp32 epilogue to C.
// ---------------------------------------------------------------------------
#define ROWB 80
#define A_BYTES (128 * ROWB)            // 10240
#define B_BYTES (256 * ROWB)            // 20480
#define STG_BYTES (2 * A_BYTES + 2 * B_BYTES)   // 61440
#define NSTAGE 3
#define GSMEM (NSTAGE * STG_BYTES)      // 184320

__device__ __forceinline__ void fill_stage(uint32_t stg,
        const __nv_bfloat16* ah, const __nv_bfloat16* al,
        const __nv_bfloat16* bh, const __nv_bfloat16* bl,
        int k0, int t) {
    {
        int row = t >> 2, cc = t & 3;
        uint32_t so = (uint32_t)(row * ROWB + cc * 16);
        size_t g = (size_t)row * DIMN + k0 + cc * 8;
        cp_async16_s(stg + so,           ah + g);
        cp_async16_s(stg + A_BYTES + so, al + g);
    }
    #pragma unroll
    for (int i = 0; i < 2; i++) {
        int c = t + (i << 9);
        int row = c >> 2, cc = c & 3;
        uint32_t so = (uint32_t)(row * ROWB + cc * 16);
        size_t g = (size_t)row * DIMN + k0 + cc * 8;
        cp_async16_s(stg + 2 * A_BYTES + so,           bh + g);
        cp_async16_s(stg + 2 * A_BYTES + B_BYTES + so, bl + g);
    }
}

template <int MODE>
__global__ __launch_bounds__(512)
void hgemm3(const __nv_bfloat16* __restrict__ Ah, const __nv_bfloat16* __restrict__ Al,
            const __nv_bfloat16* __restrict__ Bh, const __nv_bfloat16* __restrict__ Bl,
            float* __restrict__ C,
            __nv_bfloat16* __restrict__ qh, __nv_bfloat16* __restrict__ ql,
            __nv_bfloat16* __restrict__ kh, __nv_bfloat16* __restrict__ kl,
            __nv_bfloat16* __restrict__ vh, __nv_bfloat16* __restrict__ vl) {
    extern __shared__ char dsm[];
    const uint32_t base = smem_u32(dsm);

    const int t    = threadIdx.x;
    const int lane = t & 31;
    const int warp = t >> 5;              // 0..15
    const int wm   = warp & 3;            // m offset 32*wm
    const int wn   = warp >> 2;           // n offset 64*wn
    const int bm   = blockIdx.y << 7;
    const int bn   = blockIdx.x << 8;     // 256-wide tiles

    const __nv_bfloat16* ah0 = Ah + (size_t)bm * DIMN;
    const __nv_bfloat16* al0 = Al + (size_t)bm * DIMN;
    const __nv_bfloat16* bh0 = Bh + (size_t)bn * DIMN;
    const __nv_bfloat16* bl0 = Bl + (size_t)bn * DIMN;

    const int nloc = bn & 2047;

    float acc[2][8][4];
    #pragma unroll
    for (int mi = 0; mi < 2; mi++)
        #pragma unroll
        for (int ni = 0; ni < 8; ni++)
            #pragma unroll
            for (int e = 0; e < 4; e++) acc[mi][ni][e] = 0.f;

    const uint32_t a_lrow  = (uint32_t)(lane & 15);
    const uint32_t a_khalf = (uint32_t)(lane >> 4) * 16;

    fill_stage(base, ah0, al0, bh0, bl0, 0, t);
    CP_COMMIT();
    fill_stage(base + STG_BYTES, ah0, al0, bh0, bl0, 32, t);
    CP_COMMIT();

    const int NT = DIMN / 32;   // 64
    uint32_t sidx = 0, fidx = 2;
    for (int kt = 0; kt < NT; kt++) {
        if (kt + 2 < NT) {
            fill_stage(base + fidx * STG_BYTES, ah0, al0, bh0, bl0,
                       (kt + 2) * 32, t);
            CP_COMMIT();
            asm volatile("cp.async.wait_group 2;\n");
        } else {
            asm volatile("cp.async.wait_group 0;\n");
        }
        __syncthreads();

        const uint32_t stg  = base + sidx * STG_BYTES;
        const uint32_t As_h = stg;
        const uint32_t As_l = stg + A_BYTES;
        const uint32_t Bs_h = stg + 2 * A_BYTES;
        const uint32_t Bs_l = stg + 2 * A_BYTES + B_BYTES;

        #pragma unroll
        for (int ks = 0; ks < 2; ks++) {
            const uint32_t kb = (uint32_t)ks * 32;
            uint32_t Afh[2][4], Afl[2][4];
            #pragma unroll
            for (int mi = 0; mi < 2; mi++) {
                uint32_t ro = (uint32_t)(wm * 32 + mi * 16) + a_lrow;
                uint32_t off = ro * ROWB + kb + a_khalf;
                ldsm_x4(As_h + off, Afh[mi]);
                ldsm_x4(As_l + off, Afl[mi]);
            }
            #pragma unroll
            for (int nj = 0; nj < 4; nj++) {
                uint32_t ro = (uint32_t)(wn * 64 + nj * 16) + a_lrow;
                uint32_t off = ro * ROWB + kb + a_khalf;
                uint32_t rh[4], rl[4];
                ldsm_x4(Bs_h + off, rh);
                ldsm_x4(Bs_l + off, rl);
                // term Ah*Bh: 4 independent mmas
                mma_bf16_2(acc[0][2*nj],   Afh[0], rh[0], rh[2]);
                mma_bf16_2(acc[1][2*nj],   Afh[1], rh[0], rh[2]);
                mma_bf16_2(acc[0][2*nj+1], Afh[0], rh[1], rh[3]);
                mma_bf16_2(acc[1][2*nj+1], Afh[1], rh[1], rh[3]);
                // term Al*Bh: 4 independent mmas (acc reuse distance 4)
                mma_bf16_2(acc[0][2*nj],   Afl[0], rh[0], rh[2]);
                mma_bf16_2(acc[1][2*nj],   Afl[1], rh[0], rh[2]);
                mma_bf16_2(acc[0][2*nj+1], Afl[0], rh[1], rh[3]);
                mma_bf16_2(acc[1][2*nj+1], Afl[1], rh[1], rh[3]);
                // term Ah*Bl: 4 independent mmas
                mma_bf16_2(acc[0][2*nj],   Afh[0], rl[0], rl[2]);
                mma_bf16_2(acc[1][2*nj],   Afh[1], rl[0], rl[2]);
                mma_bf16_2(acc[0][2*nj+1], Afh[0], rl[1], rl[3]);
                mma_bf16_2(acc[1][2*nj+1], Afh[1], rl[1], rl[3]);
            }
        }
        __syncthreads();

        sidx = (sidx + 1 == NSTAGE) ? 0 : sidx + 1;
        fidx = (fidx + 1 == NSTAGE) ? 0 : fidx + 1;
    }

    const int gr = lane >> 2, tg = lane & 3;
    if (MODE == 1) {
        #pragma unroll
        for (int mi = 0; mi < 2; mi++) {
            #pragma unroll
            for (int ni = 0; ni < 8; ni++) {
                const int m = bm + wm * 32 + mi * 16 + gr;
                const int n = nloc + wn * 64 + ni * 8 + tg * 2;
                *(float2*)(C + (size_t)m * DIMN + n) =
                    make_float2(acc[mi][ni][0], acc[mi][ni][1]);
                *(float2*)(C + (size_t)(m + 8) * DIMN + n) =
                    make_float2(acc[mi][ni][2], acc[mi][ni][3]);
            }
        }
    } else {
        const int gm = bn >> 11;                 // 0=q, 1=k, 2=v
        __nv_bfloat16 *oh, *ol;
        if (gm == 0)      { oh = qh; ol = ql; }
        else if (gm == 1) { oh = kh; ol = kl; }
        else              { oh = vh; ol = vl; }
        const bool dorope = (gm < 2);
        #pragma unroll
        for (int mi = 0; mi < 2; mi++) {
            #pragma unroll
            for (int ni = 0; ni < 8; ni++) {
                const int n  = nloc + wn * 64 + ni * 8 + tg * 2;
                const int r0 = bm + wm * 32 + mi * 16 + gr;
                float v0 = acc[mi][ni][0], v1 = acc[mi][ni][1];
                float v2 = acc[mi][ni][2], v3 = acc[mi][ni][3];
                if (dorope) {
                    int dp = (n >> 1) & 63;
                    float2 c0 = g_rope[(size_t)(r0 & (SS - 1)) * 64 + dp];
                    float2 c1 = g_rope[(size_t)((r0 + 8) & (SS - 1)) * 64 + dp];
                    float t0 = v0 * c0.x - v1 * c0.y, t1 = v0 * c0.y + v1 * c0.x;
                    v0 = t0; v1 = t1;
                    float t2 = v2 * c1.x - v3 * c1.y, t3 = v2 * c1.y + v3 * c1.x;
                    v2 = t2; v3 = t3;
                }
                split_store(oh, ol, (size_t)r0 * DIMN + n, v0, v1);
                split_store(oh, ol, (size_t)(r0 + 8) * DIMN + n, v2, v3);
            }
        }
    }
}

// ---------------------------------------------------------------------------
// flash2: tensor-core causal flash attention, BM=BN=64, 256 threads.
// Term-grouped mma ordering throughout. Emits bf16 hi/lo output.
// ---------------------------------------------------------------------------
#define FRB 272                 // Q/K/V smem row bytes (128 bf16 + 8 pad)
#define PRB 144                 // P smem row bytes (64 bf16 + 8 pad)
#define SST 66                  // Ss fp32 stride
#define OFF_QH 0
#define OFF_QL 17408
#define OFF_KH 34816
#define OFF_KL 52224
#define OFF_VH 69632
#define OFF_VL 87040
#define OFF_SSX 104448
#define OFF_PH 121344
#define OFF_PL 130560
#define OFF_CORR 139776
#define OFF_LINV 140032
#define FLASH2_SMEM 140288

__global__ __launch_bounds__(256, 1)
void flash2(const __nv_bfloat16* __restrict__ Qh, const __nv_bfloat16* __restrict__ Ql,
            const __nv_bfloat16* __restrict__ Kh, const __nv_bfloat16* __restrict__ Kl,
            const __nv_bfloat16* __restrict__ Vh, const __nv_bfloat16* __restrict__ Vl,
            __nv_bfloat16* __restrict__ Ath, __nv_bfloat16* __restrict__ Atl) {
    extern __shared__ char fsm[];
    const uint32_t base = smem_u32(fsm);
    float* Ssf    = (float*)(fsm + OFF_SSX);
    float* scorrf = (float*)(fsm + OFF_CORR);
    float* linvf  = (float*)(fsm + OFF_LINV);
    __nv_bfloat16* Psh = (__nv_bfloat16*)(fsm + OFF_PH);
    __nv_bfloat16* Psl = (__nv_bfloat16*)(fsm + OFF_PL);

    const int t = threadIdx.x, lane = t & 31, warp = t >> 5;
    const int qt = blockIdx.x, h = blockIdx.y, b = blockIdx.z;
    const int q0 = qt * 64;
    const float scale = 0.08838834764831845f;   // 1/sqrt(128)

    const size_t hoff = ((size_t)b * SS) * DIMN + (size_t)h * HDD;
    const __nv_bfloat16* qh = Qh + hoff;
    const __nv_bfloat16* ql = Ql + hoff;
    const __nv_bfloat16* kh = Kh + hoff;
    const __nv_bfloat16* kl = Kl + hoff;
    const __nv_bfloat16* vh = Vh + hoff;
    const __nv_bfloat16* vl = Vl + hoff;

    #pragma unroll
    for (int i = 0; i < 4; i++) {
        int c = t + (i << 8);
        int row = c >> 4, cc = c & 15;
        uint32_t so = (uint32_t)(row * FRB + cc * 16);
        size_t g = (size_t)(q0 + row) * DIMN + cc * 8;
        cp_async16_s(base + OFF_QH + so, qh + g);
        cp_async16_s(base + OFF_QL + so, ql + g);
    }
    CP_COMMIT();

    const int m0  = (warp >> 1) * 16;
    const int n0q = (warp & 1) * 32;
    const int n0p = (warp & 1) * 64;
    const int gr = lane >> 2, tg = lane & 3;
    const int sr = t >> 2, q4 = t & 3;

    const uint32_t a_lrow = (uint32_t)(lane & 15);
    const uint32_t a_kh   = (uint32_t)(lane >> 4) * 16;

    float oacc[8][4];
    #pragma unroll
    for (int ni = 0; ni < 8; ni++)
        #pragma unroll
        for (int e = 0; e < 4; e++) oacc[ni][e] = 0.f;
    float mval = -CUDART_INF_F, lval = 0.f;

    for (int kt = 0; kt <= qt; kt++) {
        const int k0 = kt * 64;
        __syncthreads();
        #pragma unroll
        for (int i = 0; i < 4; i++) {
            int c = t + (i << 8);
            int row = c >> 4, cc = c & 15;
            uint32_t so = (uint32_t)(row * FRB + cc * 16);
            size_t g = (size_t)(k0 + row) * DIMN + cc * 8;
            cp_async16_s(base + OFF_KH + so, kh + g);
            cp_async16_s(base + OFF_KL + so, kl + g);
            cp_async16_s(base + OFF_VH + so, vh + g);
            cp_async16_s(base + OFF_VL + so, vl + g);
        }
        CP_COMMIT();
        asm volatile("cp.async.wait_group 0;\n");
        __syncthreads();

        // ---- QK^T (3-term), term-grouped: same-acc distance = 4 ----
        float sacc[4][4];
        #pragma unroll
        for (int ni = 0; ni < 4; ni++)
            #pragma unroll
            for (int e = 0; e < 4; e++) sacc[ni][e] = 0.f;
        #pragma unroll
        for (int ks = 0; ks < 8; ks++) {
            const uint32_t kb = (uint32_t)ks * 32;
            uint32_t Bfh[4][2], Bfl[4][2];
            #pragma unroll
            for (int nj = 0; nj < 2; nj++) {
                uint32_t ro = (uint32_t)(n0q + nj * 16) + a_lrow;
                uint32_t off = ro * FRB + kb + a_kh;
                uint32_t rh[4], rl[4];
                ldsm_x4(base + OFF_KH + off, rh);
                ldsm_x4(base + OFF_KL + off, rl);
                Bfh[2*nj][0] = rh[0]; Bfh[2*nj][1] = rh[2];
                Bfh[2*nj+1][0] = rh[1]; Bfh[2*nj+1][1] = rh[3];
                Bfl[2*nj][0] = rl[0]; Bfl[2*nj][1] = rl[2];
                Bfl[2*nj+1][0] = rl[1]; Bfl[2*nj+1][1] = rl[3];
            }
            uint32_t aoff = (uint32_t)(m0 + a_lrow) * FRB + kb + a_kh;
            uint32_t Afh[4], Afl[4];
            ldsm_x4(base + OFF_QH + aoff, Afh);
            ldsm_x4(base + OFF_QL + aoff, Afl);
            #pragma unroll
            for (int ni = 0; ni < 4; ni++) mma_bf16(sacc[ni], Afh, Bfh[ni]);
            #pragma unroll
            for (int ni = 0; ni < 4; ni++) mma_bf16(sacc[ni], Afl, Bfh[ni]);
            #pragma unroll
            for (int ni = 0; ni < 4; ni++) mma_bf16(sacc[ni], Afh, Bfl[ni]);
        }
        #pragma unroll
        for (int ni = 0; ni < 4; ni++) {
            int cn = n0q + ni * 8 + tg * 2;
            int r0 = m0 + gr, r1 = r0 + 8;
            float s0 = sacc[ni][0] * scale, s1 = sacc[ni][1] * scale;
            float s2 = sacc[ni][2] * scale, s3 = sacc[ni][3] * scale;
            if (k0 + cn     > q0 + r0) s0 = -CUDART_INF_F;
            if (k0 + cn + 1 > q0 + r0) s1 = -CUDART_INF_F;
            if (k0 + cn     > q0 + r1) s2 = -CUDART_INF_F;
            if (k0 + cn + 1 > q0 + r1) s3 = -CUDART_INF_F;
            Ssf[r0 * SST + cn]     = s0;
            Ssf[r0 * SST + cn + 1] = s1;
            Ssf[r1 * SST + cn]     = s2;
            Ssf[r1 * SST + cn + 1] = s3;
        }
        __syncthreads();

        // ---- online softmax (quad per row), emit P bf16 hi/lo ----
        {
            float* srow = Ssf + sr * SST + q4 * 16;
            float mloc = -CUDART_INF_F;
            #pragma unroll
            for (int j = 0; j < 16; j++) mloc = fmaxf(mloc, srow[j]);
            mloc = fmaxf(mloc, __shfl_xor_sync(0xFFFFFFFFu, mloc, 1));
            mloc = fmaxf(mloc, __shfl_xor_sync(0xFFFFFFFFu, mloc, 2));
            float mnew = fmaxf(mval, mloc);
            float corr = __expf(mval - mnew);
            if (q4 == 0) scorrf[sr] = corr;
            __nv_bfloat16* php = Psh + sr * (PRB / 2) + q4 * 16;
            __nv_bfloat16* plp = Psl + sr * (PRB / 2) + q4 * 16;
            float lloc = 0.f;
            #pragma unroll
            for (int j = 0; j < 16; j++) {
                float p = __expf(srow[j] - mnew);
                __nv_bfloat16 ph = __float2bfloat16(p);
                php[j] = ph;
                plp[j] = __float2bfloat16(p - __bfloat162float(ph));
                lloc += p;
            }
            lloc += __shfl_xor_sync(0xFFFFFFFFu, lloc, 1);
            lloc += __shfl_xor_sync(0xFFFFFFFFu, lloc, 2);
            lval = lval * corr + lloc;
            mval = mnew;
        }
        __syncthreads();

        // ---- rescale, then P@V (3-term), term-grouped: distance = 8 ----
        {
            float c0 = scorrf[m0 + gr], c1 = scorrf[m0 + gr + 8];
            #pragma unroll
            for (int ni = 0; ni < 8; ni++) {
                oacc[ni][0] *= c0; oacc[ni][1] *= c0;
                oacc[ni][2] *= c1; oacc[ni][3] *= c1;
            }
        }
        #pragma unroll
        for (int ks = 0; ks < 4; ks++) {
            uint32_t aoff = (uint32_t)(m0 + a_lrow) * PRB + (uint32_t)ks * 32 + a_kh;
            uint32_t Afh[4], Afl[4];
            ldsm_x4(base + OFF_PH + aoff, Afh);
            ldsm_x4(base + OFF_PL + aoff, Afl);
            uint32_t vrow = (uint32_t)(ks * 16) + a_lrow;
            uint32_t vhr[4][4], vlr[4][4];
            #pragma unroll
            for (int nj = 0; nj < 4; nj++) {
                uint32_t boff = vrow * FRB +
                    (uint32_t)(n0p + nj * 16 + ((lane >> 4) << 3)) * 2;
                ldsm_x4_t(base + OFF_VH + boff, vhr[nj]);
                ldsm_x4_t(base + OFF_VL + boff, vlr[nj]);
            }
            // term Ph*Vh
            #pragma unroll
            for (int nj = 0; nj < 4; nj++) {
                mma_bf16_2(oacc[2*nj],   Afh, vhr[nj][0], vhr[nj][1]);
                mma_bf16_2(oacc[2*nj+1], Afh, vhr[nj][2], vhr[nj][3]);
            }
            // term Pl*Vh
            #pragma unroll
            for (int nj = 0; nj < 4; nj++) {
                mma_bf16_2(oacc[2*nj],   Afl, vhr[nj][0], vhr[nj][1]);
                mma_bf16_2(oacc[2*nj+1], Afl, vhr[nj][2], vhr[nj][3]);
            }
            // term Ph*Vl
            #pragma unroll
            for (int nj = 0; nj < 4; nj++) {
                mma_bf16_2(oacc[2*nj],   Afh, vlr[nj][0], vlr[nj][1]);
                mma_bf16_2(oacc[2*nj+1], Afh, vlr[nj][2], vlr[nj][3]);
            }
        }
    }

    __syncthreads();
    if (q4 == 0) linvf[sr] = 1.f / lval;
    __syncthreads();

    const float i0v = linvf[m0 + gr], i1v = linvf[m0 + gr + 8];
    __nv_bfloat16* ath = Ath + hoff;
    __nv_bfloat16* atl = Atl + hoff;
    #pragma unroll
    for (int ni = 0; ni < 8; ni++) {
        int col = n0p + ni * 8 + tg * 2;
        split_store(ath, atl, (size_t)(q0 + m0 + gr) * DIMN + col,
                    oacc[ni][0] * i0v, oacc[ni][1] * i0v);
        split_store(ath, atl, (size_t)(q0 + m0 + gr + 8) * DIMN + col,
                    oacc[ni][2] * i1v, oacc[ni][3] * i1v);
    }
}

// ---------------------------------------------------------------------------
extern "C" void kernel_launch(void* const* d_in, const int* in_sizes, int n_in,
                              void* d_out, int out_size) {
    const float* x  = (const float*)d_in[0];
    const float* Wq = (const float*)d_in[1];
    const float* Wk = (const float*)d_in[2];
    const float* Wv = (const float*)d_in[3];
    const float* Wo = (const float*)d_in[4];
    float* out = (float*)d_out;

    __nv_bfloat16 *xh, *xl, *ath, *atl, *wth, *wtl;
    __nv_bfloat16 *qh, *ql, *kh, *kl, *vh, *vl;
    cudaGetSymbolAddress((void**)&xh,  g_xh);
    cudaGetSymbolAddress((void**)&xl,  g_xl);
    cudaGetSymbolAddress((void**)&ath, g_ath);
    cudaGetSymbolAddress((void**)&atl, g_atl);
    cudaGetSymbolAddress((void**)&wth, g_wth);
    cudaGetSymbolAddress((void**)&wtl, g_wtl);
    cudaGetSymbolAddress((void**)&qh,  g_qh);
    cudaGetSymbolAddress((void**)&ql,  g_ql);
    cudaGetSymbolAddress((void**)&kh,  g_kh);
    cudaGetSymbolAddress((void**)&kl,  g_kl);
    cudaGetSymbolAddress((void**)&vh,  g_vh);
    cudaGetSymbolAddress((void**)&vl,  g_vl);
    const size_t WSZ = (size_t)DIMN * DIMN;

    cudaFuncSetAttribute(hgemm3<0>,
                         cudaFuncAttributeMaxDynamicSharedMemorySize, GSMEM);
    cudaFuncSetAttribute(hgemm3<1>,
                         cudaFuncAttributeMaxDynamicSharedMemorySize, GSMEM);
    cudaFuncSetAttribute(flash2,
                         cudaFuncAttributeMaxDynamicSharedMemorySize, FLASH2_SMEM);

    // idx 0-2: prep; idx 3 = fused QKV GEMM (ncu capture slot)
    split_rows<<<(MTOT * DIMN) / 1024, 256>>>(x, xh, xl);
    dim3 tga(DIMN / 32, DIMN / 32, 4), tb(32, 8);
    split_transpose_all<<<tga, tb>>>(Wq, Wk, Wv, Wo, wth, wtl);
    rope_table<<<(SS * 64) / 256, 256>>>();

    dim3 gqkv(3 * DIMN / 256, MTOT / 128);   // (24, 32)
    hgemm3<0><<<gqkv, 512, GSMEM>>>(xh, xl, wth, wtl, nullptr,
                                    qh, ql, kh, kl, vh, vl);

    flash2<<<dim3(SS / 64, HH, BB), 256, FLASH2_SMEM>>>(qh, ql, kh, kl, vh, vl,
                                                        ath, atl);

    dim3 go(DIMN / 256, MTOT / 128);         // (8, 32)
    hgemm3<1><<<go, 512, GSMEM>>>(ath, atl, wth + 3 * WSZ, wtl + 3 * WSZ, out,
                                  nullptr, nullptr, nullptr, nullptr,
                                  nullptr, nullptr);
}

// round 13
// speedup vs baseline: 1.5249x; 1.4740x over previous
#include <cuda_runtime.h>
#include <cuda_fp16.h>
#include <math_constants.h>
#include <math.h>
#include <cstdint>

#define DIMN 2048
#define BB 2
#define SS 2048
#define HH 16
#define HDD 128
#define MTOT (BB*SS)   // 4096

// ---------------------------------------------------------------------------
// Scratch (alloc-free rule: __device__ globals)
// ---------------------------------------------------------------------------
__device__ __half g_xh[(size_t)MTOT * DIMN];
__device__ __half g_xl[(size_t)MTOT * DIMN];
__device__ __half g_ath[(size_t)MTOT * DIMN];
__device__ __half g_atl[(size_t)MTOT * DIMN];
__device__ __half g_wth[4][(size_t)DIMN * DIMN];   // W^T hi, [N][K]
__device__ __half g_qh[(size_t)MTOT * DIMN];
__device__ __half g_ql[(size_t)MTOT * DIMN];
__device__ __half g_kh[(size_t)MTOT * DIMN];
__device__ __half g_vh[(size_t)MTOT * DIMN];
__device__ float2 g_rope[(size_t)SS * 64];         // (cos, sin) per (s, dp)

// ---------------------------------------------------------------------------
// PTX helpers (generic sm_80+ features only)
// ---------------------------------------------------------------------------
__device__ __forceinline__ void cp_async16_s(uint32_t s, const void* g) {
    asm volatile("cp.async.cg.shared.global [%0], [%1], 16;\n" :: "r"(s), "l"(g));
}
#define CP_COMMIT() asm volatile("cp.async.commit_group;\n")

__device__ __forceinline__ uint32_t smem_u32(const void* p) {
    uint32_t a;
    asm("{ .reg .u64 t; cvta.to.shared.u64 t, %1; cvt.u32.u64 %0, t; }"
        : "=r"(a) : "l"(p));
    return a;
}

__device__ __forceinline__ void ldsm_x4(uint32_t addr, uint32_t* r) {
    asm volatile("ldmatrix.sync.aligned.m8n8.x4.shared.b16 {%0,%1,%2,%3}, [%4];"
                 : "=r"(r[0]), "=r"(r[1]), "=r"(r[2]), "=r"(r[3]) : "r"(addr));
}
__device__ __forceinline__ void ldsm_x4_t(uint32_t addr, uint32_t* r) {
    asm volatile("ldmatrix.sync.aligned.m8n8.x4.trans.shared.b16 {%0,%1,%2,%3}, [%4];"
                 : "=r"(r[0]), "=r"(r[1]), "=r"(r[2]), "=r"(r[3]) : "r"(addr));
}

__device__ __forceinline__ void mma_f16(float* d, const uint32_t* a,
                                        uint32_t b0, uint32_t b1) {
    asm volatile(
        "mma.sync.aligned.m16n8k16.row.col.f32.f16.f16.f32 "
        "{%0,%1,%2,%3}, {%4,%5,%6,%7}, {%8,%9}, {%0,%1,%2,%3};"
        : "+f"(d[0]), "+f"(d[1]), "+f"(d[2]), "+f"(d[3])
        : "r"(a[0]), "r"(a[1]), "r"(a[2]), "r"(a[3]), "r"(b0), "r"(b1));
}

__device__ __forceinline__ void split_store(__half* h, __half* l,
                                            size_t off, float v0, float v1) {
    __half h0 = __float2half(v0), h1 = __float2half(v1);
    *(__half2*)(h + off) = __half2(h0, h1);
    *(__half2*)(l + off) = __half2(
        __float2half(v0 - __half2float(h0)),
        __float2half(v1 - __half2float(h1)));
}

// ---------------------------------------------------------------------------
// Prep: split fp32 rows into fp16 hi/lo
// ---------------------------------------------------------------------------
__global__ void split_rows(const float* __restrict__ in,
                           __half* __restrict__ h,
                           __half* __restrict__ l) {
    size_t i = ((size_t)blockIdx.x * 256 + threadIdx.x) * 4;
    float4 v = *(const float4*)(in + i);
    split_store(h, l, i,     v.x, v.y);
    split_store(h, l, i + 2, v.z, v.w);
}

// ---------------------------------------------------------------------------
// Prep: transpose all 4 weights (blockIdx.z selects) -> W^T fp16 hi
// ---------------------------------------------------------------------------
__global__ void split_transpose_all(const float* __restrict__ W0,
                                    const float* __restrict__ W1,
                                    const float* __restrict__ W2,
                                    const float* __restrict__ W3,
                                    __half* __restrict__ th) {
    __shared__ float ts[32][33];
    const float* W = (blockIdx.z == 0) ? W0 : (blockIdx.z == 1) ? W1
                   : (blockIdx.z == 2) ? W2 : W3;
    const size_t mo = (size_t)blockIdx.z * DIMN * DIMN;
    const int bx = blockIdx.x * 32, by = blockIdx.y * 32;
    const int tx = threadIdx.x, ty = threadIdx.y;   // 32 x 8
    #pragma unroll
    for (int j = 0; j < 4; j++)
        ts[ty + 8 * j][tx] = W[(size_t)(by + ty + 8 * j) * DIMN + bx + tx];
    __syncthreads();
    #pragma unroll
    for (int j = 0; j < 4; j++) {
        float v = ts[tx][ty + 8 * j];
        th[mo + (size_t)(bx + ty + 8 * j) * DIMN + by + tx] = __float2half(v);
    }
}

// ---------------------------------------------------------------------------
// Prep: RoPE cos/sin table  g_rope[s][dp]
// ---------------------------------------------------------------------------
__global__ void rope_table() {
    int idx = blockIdx.x * 256 + threadIdx.x;    // 0 .. SS*64-1
    int s = idx >> 6, dp = idx & 63;
    float inv = powf(10000.0f, -(float)dp * (1.0f / 64.0f));
    float sn, cs;
    sincosf((float)s * inv, &sn, &cs);
    g_rope[idx] = make_float2(cs, sn);
}

// ---------------------------------------------------------------------------
// fp16 2-term split GEMM: C = Ah@Bh^T + Al@Bh^T (B hi only).
// Block tile 128x256, BK=32, 512 threads (16 warps, warp tile 32x64),
// 3-stage cp.async, term-grouped mma.
// MODE 0: QKV epilogue — RoPE via table; q -> hi/lo, k,v -> hi only.
// MODE 1: plain fp32 epilogue to C.
// ---------------------------------------------------------------------------
#define ROWB 80
#define A_BYTES (128 * ROWB)            // 10240
#define B_BYTES (256 * ROWB)            // 20480
#define STG_BYTES (2 * A_BYTES + B_BYTES)   // 40960
#define NSTAGE 3
#define GSMEM (NSTAGE * STG_BYTES)      // 122880

__device__ __forceinline__ void fill_stage(uint32_t stg,
        const __half* ah, const __half* al, const __half* bh,
        int k0, int t) {
    {
        int row = t >> 2, cc = t & 3;
        uint32_t so = (uint32_t)(row * ROWB + cc * 16);
        size_t g = (size_t)row * DIMN + k0 + cc * 8;
        cp_async16_s(stg + so,           ah + g);
        cp_async16_s(stg + A_BYTES + so, al + g);
    }
    #pragma unroll
    for (int i = 0; i < 2; i++) {
        int c = t + (i << 9);
        int row = c >> 2, cc = c & 3;
        uint32_t so = (uint32_t)(row * ROWB + cc * 16);
        size_t g = (size_t)row * DIMN + k0 + cc * 8;
        cp_async16_s(stg + 2 * A_BYTES + so, bh + g);
    }
}

template <int MODE>
__global__ __launch_bounds__(512)
void hgemm2(const __half* __restrict__ Ah, const __half* __restrict__ Al,
            const __half* __restrict__ Bh,
            float* __restrict__ C,
            __half* __restrict__ qh, __half* __restrict__ ql,
            __half* __restrict__ kh, __half* __restrict__ vh) {
    extern __shared__ char dsm[];
    const uint32_t base = smem_u32(dsm);

    const int t    = threadIdx.x;
    const int lane = t & 31;
    const int warp = t >> 5;              // 0..15
    const int wm   = warp & 3;            // m offset 32*wm
    const int wn   = warp >> 2;           // n offset 64*wn
    const int bm   = blockIdx.y << 7;
    const int bn   = blockIdx.x << 8;     // 256-wide tiles

    const __half* ah0 = Ah + (size_t)bm * DIMN;
    const __half* al0 = Al + (size_t)bm * DIMN;
    const __half* bh0 = Bh + (size_t)bn * DIMN;

    const int nloc = bn & 2047;

    float acc[2][8][4];
    #pragma unroll
    for (int mi = 0; mi < 2; mi++)
        #pragma unroll
        for (int ni = 0; ni < 8; ni++)
            #pragma unroll
            for (int e = 0; e < 4; e++) acc[mi][ni][e] = 0.f;

    const uint32_t a_lrow  = (uint32_t)(lane & 15);
    const uint32_t a_khalf = (uint32_t)(lane >> 4) * 16;

    fill_stage(base, ah0, al0, bh0, 0, t);
    CP_COMMIT();
    fill_stage(base + STG_BYTES, ah0, al0, bh0, 32, t);
    CP_COMMIT();

    const int NT = DIMN / 32;   // 64
    uint32_t sidx = 0, fidx = 2;
    for (int kt = 0; kt < NT; kt++) {
        if (kt + 2 < NT) {
            fill_stage(base + fidx * STG_BYTES, ah0, al0, bh0,
                       (kt + 2) * 32, t);
            CP_COMMIT();
            asm volatile("cp.async.wait_group 2;\n");
        } else {
            asm volatile("cp.async.wait_group 0;\n");
        }
        __syncthreads();

        const uint32_t stg  = base + sidx * STG_BYTES;
        const uint32_t As_h = stg;
        const uint32_t As_l = stg + A_BYTES;
        const uint32_t Bs_h = stg + 2 * A_BYTES;

        #pragma unroll
        for (int ks = 0; ks < 2; ks++) {
            const uint32_t kb = (uint32_t)ks * 32;
            uint32_t Afh[2][4], Afl[2][4];
            #pragma unroll
            for (int mi = 0; mi < 2; mi++) {
                uint32_t ro = (uint32_t)(wm * 32 + mi * 16) + a_lrow;
                uint32_t off = ro * ROWB + kb + a_khalf;
                ldsm_x4(As_h + off, Afh[mi]);
                ldsm_x4(As_l + off, Afl[mi]);
            }
            #pragma unroll
            for (int nj = 0; nj < 4; nj++) {
                uint32_t ro = (uint32_t)(wn * 64 + nj * 16) + a_lrow;
                uint32_t off = ro * ROWB + kb + a_khalf;
                uint32_t rh[4];
                ldsm_x4(Bs_h + off, rh);
                // term Ah*Bh: 4 independent mmas
                mma_f16(acc[0][2*nj],   Afh[0], rh[0], rh[2]);
                mma_f16(acc[1][2*nj],   Afh[1], rh[0], rh[2]);
                mma_f16(acc[0][2*nj+1], Afh[0], rh[1], rh[3]);
                mma_f16(acc[1][2*nj+1], Afh[1], rh[1], rh[3]);
                // term Al*Bh: 4 independent mmas (acc reuse distance 4)
                mma_f16(acc[0][2*nj],   Afl[0], rh[0], rh[2]);
                mma_f16(acc[1][2*nj],   Afl[1], rh[0], rh[2]);
                mma_f16(acc[0][2*nj+1], Afl[0], rh[1], rh[3]);
                mma_f16(acc[1][2*nj+1], Afl[1], rh[1], rh[3]);
            }
        }
        __syncthreads();

        sidx = (sidx + 1 == NSTAGE) ? 0 : sidx + 1;
        fidx = (fidx + 1 == NSTAGE) ? 0 : fidx + 1;
    }

    const int gr = lane >> 2, tg = lane & 3;
    if (MODE == 1) {
        #pragma unroll
        for (int mi = 0; mi < 2; mi++) {
            #pragma unroll
            for (int ni = 0; ni < 8; ni++) {
                const int m = bm + wm * 32 + mi * 16 + gr;
                const int n = nloc + wn * 64 + ni * 8 + tg * 2;
                *(float2*)(C + (size_t)m * DIMN + n) =
                    make_float2(acc[mi][ni][0], acc[mi][ni][1]);
                *(float2*)(C + (size_t)(m + 8) * DIMN + n) =
                    make_float2(acc[mi][ni][2], acc[mi][ni][3]);
            }
        }
    } else {
        const int gm = bn >> 11;                 // 0=q, 1=k, 2=v
        const bool dorope = (gm < 2);
        #pragma unroll
        for (int mi = 0; mi < 2; mi++) {
            #pragma unroll
            for (int ni = 0; ni < 8; ni++) {
                const int n  = nloc + wn * 64 + ni * 8 + tg * 2;
                const int r0 = bm + wm * 32 + mi * 16 + gr;
                float v0 = acc[mi][ni][0], v1 = acc[mi][ni][1];
                float v2 = acc[mi][ni][2], v3 = acc[mi][ni][3];
                if (dorope) {
                    int dp = (n >> 1) & 63;
                    float2 c0 = g_rope[(size_t)(r0 & (SS - 1)) * 64 + dp];
                    float2 c1 = g_rope[(size_t)((r0 + 8) & (SS - 1)) * 64 + dp];
                    float t0 = v0 * c0.x - v1 * c0.y, t1 = v0 * c0.y + v1 * c0.x;
                    v0 = t0; v1 = t1;
                    float t2 = v2 * c1.x - v3 * c1.y, t3 = v2 * c1.y + v3 * c1.x;
                    v2 = t2; v3 = t3;
                }
                size_t o0 = (size_t)r0 * DIMN + n;
                size_t o1 = (size_t)(r0 + 8) * DIMN + n;
                if (gm == 0) {
                    split_store(qh, ql, o0, v0, v1);
                    split_store(qh, ql, o1, v2, v3);
                } else {
                    __half* dst = (gm == 1) ? kh : vh;
                    *(__half2*)(dst + o0) = __floats2half2_rn(v0, v1);
                    *(__half2*)(dst + o1) = __floats2half2_rn(v2, v3);
                }
            }
        }
    }
}

// ---------------------------------------------------------------------------
// flash2: fp16 2-term tensor-core causal flash attention, BM=BN=64, 256 thr.
// QK: Q hi/lo x K hi. PV: P hi/lo x V hi. Emits att as fp16 hi/lo.
// ---------------------------------------------------------------------------
#define FRB 272                 // Q/K/V smem row bytes (128 fp16 + 16 pad)
#define PRB 144                 // P smem row bytes (64 fp16 + 16 pad)
#define SST 66                  // Ss fp32 stride
#define OFF_QH 0
#define OFF_QL 17408
#define OFF_KH 34816
#define OFF_VH 52224
#define OFF_SSX 69632
#define OFF_PH 86528
#define OFF_PL 95744
#define OFF_CORR 104960
#define OFF_LINV 105216
#define FLASH2_SMEM 105472

__global__ __launch_bounds__(256, 1)
void flash2(const __half* __restrict__ Qh, const __half* __restrict__ Ql,
            const __half* __restrict__ Kh, const __half* __restrict__ Vh,
            __half* __restrict__ Ath, __half* __restrict__ Atl) {
    extern __shared__ char fsm[];
    const uint32_t base = smem_u32(fsm);
    float* Ssf    = (float*)(fsm + OFF_SSX);
    float* scorrf = (float*)(fsm + OFF_CORR);
    float* linvf  = (float*)(fsm + OFF_LINV);
    __half* Psh = (__half*)(fsm + OFF_PH);
    __half* Psl = (__half*)(fsm + OFF_PL);

    const int t = threadIdx.x, lane = t & 31, warp = t >> 5;
    const int qt = blockIdx.x, h = blockIdx.y, b = blockIdx.z;
    const int q0 = qt * 64;
    const float scale = 0.08838834764831845f;   // 1/sqrt(128)

    const size_t hoff = ((size_t)b * SS) * DIMN + (size_t)h * HDD;
    const __half* qhp = Qh + hoff;
    const __half* qlp = Ql + hoff;
    const __half* khp = Kh + hoff;
    const __half* vhp = Vh + hoff;

    #pragma unroll
    for (int i = 0; i < 4; i++) {
        int c = t + (i << 8);
        int row = c >> 4, cc = c & 15;
        uint32_t so = (uint32_t)(row * FRB + cc * 16);
        size_t g = (size_t)(q0 + row) * DIMN + cc * 8;
        cp_async16_s(base + OFF_QH + so, qhp + g);
        cp_async16_s(base + OFF_QL + so, qlp + g);
    }
    CP_COMMIT();

    const int m0  = (warp >> 1) * 16;
    const int n0q = (warp & 1) * 32;
    const int n0p = (warp & 1) * 64;
    const int gr = lane >> 2, tg = lane & 3;
    const int sr = t >> 2, q4 = t & 3;

    const uint32_t a_lrow = (uint32_t)(lane & 15);
    const uint32_t a_kh   = (uint32_t)(lane >> 4) * 16;

    float oacc[8][4];
    #pragma unroll
    for (int ni = 0; ni < 8; ni++)
        #pragma unroll
        for (int e = 0; e < 4; e++) oacc[ni][e] = 0.f;
    float mval = -CUDART_INF_F, lval = 0.f;

    for (int kt = 0; kt <= qt; kt++) {
        const int k0 = kt * 64;
        __syncthreads();
        #pragma unroll
        for (int i = 0; i < 4; i++) {
            int c = t + (i << 8);
            int row = c >> 4, cc = c & 15;
            uint32_t so = (uint32_t)(row * FRB + cc * 16);
            size_t g = (size_t)(k0 + row) * DIMN + cc * 8;
            cp_async16_s(base + OFF_KH + so, khp + g);
            cp_async16_s(base + OFF_VH + so, vhp + g);
        }
        CP_COMMIT();
        asm volatile("cp.async.wait_group 0;\n");
        __syncthreads();

        // ---- QK^T (2-term), term-grouped ----
        float sacc[4][4];
        #pragma unroll
        for (int ni = 0; ni < 4; ni++)
            #pragma unroll
            for (int e = 0; e < 4; e++) sacc[ni][e] = 0.f;
        #pragma unroll
        for (int ks = 0; ks < 8; ks++) {
            const uint32_t kb = (uint32_t)ks * 32;
            uint32_t Bfh[4][2];
            #pragma unroll
            for (int nj = 0; nj < 2; nj++) {
                uint32_t ro = (uint32_t)(n0q + nj * 16) + a_lrow;
                uint32_t off = ro * FRB + kb + a_kh;
                uint32_t rh[4];
                ldsm_x4(base + OFF_KH + off, rh);
                Bfh[2*nj][0] = rh[0]; Bfh[2*nj][1] = rh[2];
                Bfh[2*nj+1][0] = rh[1]; Bfh[2*nj+1][1] = rh[3];
            }
            uint32_t aoff = (uint32_t)(m0 + a_lrow) * FRB + kb + a_kh;
            uint32_t Afh[4], Afl[4];
            ldsm_x4(base + OFF_QH + aoff, Afh);
            ldsm_x4(base + OFF_QL + aoff, Afl);
            #pragma unroll
            for (int ni = 0; ni < 4; ni++)
                mma_f16(sacc[ni], Afh, Bfh[ni][0], Bfh[ni][1]);
            #pragma unroll
            for (int ni = 0; ni < 4; ni++)
                mma_f16(sacc[ni], Afl, Bfh[ni][0], Bfh[ni][1]);
        }
        #pragma unroll
        for (int ni = 0; ni < 4; ni++) {
            int cn = n0q + ni * 8 + tg * 2;
            int r0 = m0 + gr, r1 = r0 + 8;
            float s0 = sacc[ni][0] * scale, s1 = sacc[ni][1] * scale;
            float s2 = sacc[ni][2] * scale, s3 = sacc[ni][3] * scale;
            if (k0 + cn     > q0 + r0) s0 = -CUDART_INF_F;
            if (k0 + cn + 1 > q0 + r0) s1 = -CUDART_INF_F;
            if (k0 + cn     > q0 + r1) s2 = -CUDART_INF_F;
            if (k0 + cn + 1 > q0 + r1) s3 = -CUDART_INF_F;
            Ssf[r0 * SST + cn]     = s0;
            Ssf[r0 * SST + cn + 1] = s1;
            Ssf[r1 * SST + cn]     = s2;
            Ssf[r1 * SST + cn + 1] = s3;
        }
        __syncthreads();

        // ---- online softmax (quad per row), emit P fp16 hi/lo ----
        {
            float* srow = Ssf + sr * SST + q4 * 16;
            float mloc = -CUDART_INF_F;
            #pragma unroll
            for (int j = 0; j < 16; j++) mloc = fmaxf(mloc, srow[j]);
            mloc = fmaxf(mloc, __shfl_xor_sync(0xFFFFFFFFu, mloc, 1));
            mloc = fmaxf(mloc, __shfl_xor_sync(0xFFFFFFFFu, mloc, 2));
            float mnew = fmaxf(mval, mloc);
            float corr = __expf(mval - mnew);
            if (q4 == 0) scorrf[sr] = corr;
            __half* php = Psh + sr * (PRB / 2) + q4 * 16;
            __half* plp = Psl + sr * (PRB / 2) + q4 * 16;
            float lloc = 0.f;
            #pragma unroll
            for (int j = 0; j < 16; j++) {
                float p = __expf(srow[j] - mnew);
                __half ph = __float2half(p);
                php[j] = ph;
                plp[j] = __float2half(p - __half2float(ph));
                lloc += p;
            }
            lloc += __shfl_xor_sync(0xFFFFFFFFu, lloc, 1);
            lloc += __shfl_xor_sync(0xFFFFFFFFu, lloc, 2);
            lval = lval * corr + lloc;
            mval = mnew;
        }
        __syncthreads();

        // ---- rescale, then P@V (2-term), term-grouped ----
        {
            float c0 = scorrf[m0 + gr], c1 = scorrf[m0 + gr + 8];
            #pragma unroll
            for (int ni = 0; ni < 8; ni++) {
                oacc[ni][0] *= c0; oacc[ni][1] *= c0;
                oacc[ni][2] *= c1; oacc[ni][3] *= c1;
            }
        }
        #pragma unroll
        for (int ks = 0; ks < 4; ks++) {
            uint32_t aoff = (uint32_t)(m0 + a_lrow) * PRB + (uint32_t)ks * 32 + a_kh;
            uint32_t Afh[4], Afl[4];
            ldsm_x4(base + OFF_PH + aoff, Afh);
            ldsm_x4(base + OFF_PL + aoff, Afl);
            uint32_t vrow = (uint32_t)(ks * 16) + a_lrow;
            uint32_t vhr[4][4];
            #pragma unroll
            for (int nj = 0; nj < 4; nj++) {
                uint32_t boff = vrow * FRB +
                    (uint32_t)(n0p + nj * 16 + ((lane >> 4) << 3)) * 2;
                ldsm_x4_t(base + OFF_VH + boff, vhr[nj]);
            }
            // term Ph*Vh
            #pragma unroll
            for (int nj = 0; nj < 4; nj++) {
                mma_f16(oacc[2*nj],   Afh, vhr[nj][0], vhr[nj][1]);
                mma_f16(oacc[2*nj+1], Afh, vhr[nj][2], vhr[nj][3]);
            }
            // term Pl*Vh
            #pragma unroll
            for (int nj = 0; nj < 4; nj++) {
                mma_f16(oacc[2*nj],   Afl, vhr[nj][0], vhr[nj][1]);
                mma_f16(oacc[2*nj+1], Afl, vhr[nj][2], vhr[nj][3]);
            }
        }
    }

    __syncthreads();
    if (q4 == 0) linvf[sr] = 1.f / lval;
    __syncthreads();

    const float i0v = linvf[m0 + gr], i1v = linvf[m0 + gr + 8];
    __half* ath = Ath + hoff;
    __half* atl = Atl + hoff;
    #pragma unroll
    for (int ni = 0; ni < 8; ni++) {
        int col = n0p + ni * 8 + tg * 2;
        split_store(ath, atl, (size_t)(q0 + m0 + gr) * DIMN + col,
                    oacc[ni][0] * i0v, oacc[ni][1] * i0v);
        split_store(ath, atl, (size_t)(q0 + m0 + gr + 8) * DIMN + col,
                    oacc[ni][2] * i1v, oacc[ni][3] * i1v);
    }
}

// ---------------------------------------------------------------------------
extern "C" void kernel_launch(void* const* d_in, const int* in_sizes, int n_in,
                              void* d_out, int out_size) {
    const float* x  = (const float*)d_in[0];
    const float* Wq = (const float*)d_in[1];
    const float* Wk = (const float*)d_in[2];
    const float* Wv = (const float*)d_in[3];
    const float* Wo = (const float*)d_in[4];
    float* out = (float*)d_out;

    __half *xh, *xl, *ath, *atl, *wth, *qh, *ql, *kh, *vh;
    cudaGetSymbolAddress((void**)&xh,  g_xh);
    cudaGetSymbolAddress((void**)&xl,  g_xl);
    cudaGetSymbolAddress((void**)&ath, g_ath);
    cudaGetSymbolAddress((void**)&atl, g_atl);
    cudaGetSymbolAddress((void**)&wth, g_wth);
    cudaGetSymbolAddress((void**)&qh,  g_qh);
    cudaGetSymbolAddress((void**)&ql,  g_ql);
    cudaGetSymbolAddress((void**)&kh,  g_kh);
    cudaGetSymbolAddress((void**)&vh,  g_vh);
    const size_t WSZ = (size_t)DIMN * DIMN;

    cudaFuncSetAttribute(hgemm2<0>,
                         cudaFuncAttributeMaxDynamicSharedMemorySize, GSMEM);
    cudaFuncSetAttribute(hgemm2<1>,
                         cudaFuncAttributeMaxDynamicSharedMemorySize, GSMEM);
    cudaFuncSetAttribute(flash2,
                         cudaFuncAttributeMaxDynamicSharedMemorySize, FLASH2_SMEM);

    // idx 0-2: prep; idx 3 = fused QKV GEMM (ncu capture slot)
    split_rows<<<(MTOT * DIMN) / 1024, 256>>>(x, xh, xl);
    dim3 tga(DIMN / 32, DIMN / 32, 4), tb(32, 8);
    split_transpose_all<<<tga, tb>>>(Wq, Wk, Wv, Wo, wth);
    rope_table<<<(SS * 64) / 256, 256>>>();

    dim3 gqkv(3 * DIMN / 256, MTOT / 128);   // (24, 32)
    hgemm2<0><<<gqkv, 512, GSMEM>>>(xh, xl, wth, nullptr, qh, ql, kh, vh);

    flash2<<<dim3(SS / 64, HH, BB), 256, FLASH2_SMEM>>>(qh, ql, kh, vh,
                                                        ath, atl);

    dim3 go(DIMN / 256, MTOT / 128);         // (8, 32)
    hgemm2<1><<<go, 512, GSMEM>>>(ath, atl, wth + 3 * WSZ, out,
                                  nullptr, nullptr, nullptr, nullptr);
}